// round 2
// baseline (speedup 1.0000x reference)
#include <cuda_runtime.h>

#define NN 65536      // total nodes
#define EE 1048576    // total edges
#define NB 128        // graphs
#define NPG 512       // nodes per graph
#define FD 128        // hidden feature dim

// ---------------- device scratch (statics are allowed) ----------------
__device__ __align__(256) float d_X[NN * FD];   // current node features
__device__ __align__(256) float d_H[NN * FD];   // x @ W
__device__ __align__(256) float d_mask[NN];
__device__ __align__(256) float d_dinv[NN];
__device__ __align__(256) float d_score[NN];
__device__ __align__(256) int   d_cnt[NN];
__device__ __align__(256) int   d_off[NN + 1];
__device__ __align__(256) int   d_csr[EE];
__device__ __align__(256) int   d_alive[NB * 256];
__device__ __align__(256) float d_hg[NB * 256];

// ---------------- init ----------------
__global__ void k_init() {
    int i = blockIdx.x * blockDim.x + threadIdx.x;
    int stride = gridDim.x * blockDim.x;
    for (int j = i; j < NN; j += stride) { d_mask[j] = 1.f; d_cnt[j] = 0; }
    for (int j = i; j < NB * 256; j += stride) d_hg[j] = 0.f;
}

// ---------------- CSR build (by dst) ----------------
__global__ void k_count(const int* __restrict__ dst) {
    int i = blockIdx.x * blockDim.x + threadIdx.x;
    if (i < EE) atomicAdd(&d_cnt[dst[i]], 1);
}

__global__ void k_scan() {
    __shared__ int ps[1024];
    int t = threadIdx.x;
    int base = t * 64;
    int s = 0;
    for (int j = 0; j < 64; j++) s += d_cnt[base + j];
    ps[t] = s;
    __syncthreads();
    for (int off = 1; off < 1024; off <<= 1) {
        int v = ps[t];
        int add = (t >= off) ? ps[t - off] : 0;
        __syncthreads();
        ps[t] = v + add;
        __syncthreads();
    }
    int run = (t == 0) ? 0 : ps[t - 1];
    for (int j = 0; j < 64; j++) {
        int c = d_cnt[base + j];
        d_off[base + j] = run;
        run += c;
        d_cnt[base + j] = 0;   // reset for fill cursor
    }
    if (t == 1023) d_off[NN] = run;
}

__global__ void k_fill(const int* __restrict__ src, const int* __restrict__ dst) {
    int i = blockIdx.x * blockDim.x + threadIdx.x;
    if (i < EE) {
        int d = dst[i];
        int pos = d_off[d] + atomicAdd(&d_cnt[d], 1);
        d_csr[pos] = src[i];
    }
}

// ---------------- degree / dinv ----------------
__global__ void k_deg() {
    int i = blockIdx.x * blockDim.x + threadIdx.x;
    if (i >= NN) return;
    float m = d_mask[i];
    int e0 = d_off[i], e1 = d_off[i + 1];
    float s = 0.f;
    for (int e = e0; e < e1; e++) s += d_mask[d_csr[e]];
    float deg = m * (1.f + s);
    d_dinv[i] = rsqrtf(fmaxf(deg, 1.f));
}

// ---------------- GEMM: H[rows] = A[rows] @ W  (BM=64, BN=128, BK=16) ----------------
template <int K, bool FROMX, bool USEIDX>
__global__ void __launch_bounds__(256) k_gemm(const float* __restrict__ Ain,
                                              const float* __restrict__ W) {
    __shared__ float As[16][64];
    __shared__ float Bs[16][128];
    const float* A = FROMX ? (const float*)d_X : Ain;

    int tid = threadIdx.x;
    int tx = tid & 31, ty = tid >> 5;
    int r0 = ty * 8, c0 = tx * 4;
    int rowBase = blockIdx.x * 64;

    int a_r = tid >> 2, a_k0 = (tid & 3) * 4;
    int grow = USEIDX ? d_alive[rowBase + a_r] : (rowBase + a_r);
    int b_k = tid >> 4, b_c0 = (tid & 15) * 8;

    float acc[8][4] = {};

    for (int k0 = 0; k0 < K; k0 += 16) {
        float4 av = *(const float4*)&A[grow * K + k0 + a_k0];
        As[a_k0 + 0][a_r] = av.x;
        As[a_k0 + 1][a_r] = av.y;
        As[a_k0 + 2][a_r] = av.z;
        As[a_k0 + 3][a_r] = av.w;
        *(float4*)&Bs[b_k][b_c0]     = *(const float4*)&W[(k0 + b_k) * FD + b_c0];
        *(float4*)&Bs[b_k][b_c0 + 4] = *(const float4*)&W[(k0 + b_k) * FD + b_c0 + 4];
        __syncthreads();
#pragma unroll
        for (int kk = 0; kk < 16; kk++) {
            float4 bv = *(float4*)&Bs[kk][c0];
            float4 a0 = *(float4*)&As[kk][r0];
            float4 a1 = *(float4*)&As[kk][r0 + 4];
            float ar[8] = {a0.x, a0.y, a0.z, a0.w, a1.x, a1.y, a1.z, a1.w};
            float bc[4] = {bv.x, bv.y, bv.z, bv.w};
#pragma unroll
            for (int i = 0; i < 8; i++)
#pragma unroll
                for (int j = 0; j < 4; j++) acc[i][j] += ar[i] * bc[j];
        }
        __syncthreads();
    }
#pragma unroll
    for (int i = 0; i < 8; i++) {
        int orow = USEIDX ? d_alive[rowBase + r0 + i] : (rowBase + r0 + i);
        *(float4*)&d_H[orow * FD + c0] =
            make_float4(acc[i][0], acc[i][1], acc[i][2], acc[i][3]);
    }
}

// ---------------- GCN aggregation (fused self-loop + bias + relu + mask) ----------------
// grid (NB, 2): graph g, feature half hf (64 features). 512 threads. 128KB dyn smem.
__global__ void __launch_bounds__(512) k_agg(const float* __restrict__ bias) {
    extern __shared__ float hs[];                 // [512][64]
    __shared__ unsigned short csr_s[8192];
    __shared__ int off_s[513];
    __shared__ float mask_s[512], dinv_s[512];

    int g = blockIdx.x, hf = blockIdx.y;
    int f0 = hf * 64;
    int tid = threadIdx.x;
    int gbase = g * NPG;
    int ebase = d_off[gbase];

    for (int i = tid; i < 513; i += 512) off_s[i] = d_off[gbase + i] - ebase;
    mask_s[tid] = d_mask[gbase + tid];
    dinv_s[tid] = d_dinv[gbase + tid];
    for (int j = tid; j < 8192; j += 512)
        csr_s[j] = (unsigned short)(d_csr[ebase + j] - gbase);
    for (int idx4 = tid; idx4 < 512 * 16; idx4 += 512) {
        int row = idx4 >> 4, c4 = idx4 & 15;
        *(float4*)&hs[row * 64 + c4 * 4] =
            *(const float4*)&d_H[(gbase + row) * FD + f0 + c4 * 4];
    }
    __syncthreads();

    int w = tid >> 5, lane = tid & 31;
    float b0 = bias[f0 + 2 * lane], b1 = bias[f0 + 2 * lane + 1];

    for (int it = 0; it < 32; it++) {
        int d = w + it * 16;
        float md = mask_s[d];
        if (md == 0.f) continue;                   // dead rows stay 0 (pool zeroed them)
        float dd = dinv_s[d];
        int e0 = off_s[d], e1 = off_s[d + 1];
        float acc0 = 0.f, acc1 = 0.f;
        for (int base = e0; base < e1; base += 32) {
            int cnt = min(32, e1 - base);
            int sl_l = 0;
            float nrm_l = 0.f;
            if (lane < cnt) {
                sl_l = csr_s[base + lane];
                nrm_l = mask_s[sl_l] * dd * dinv_s[sl_l];
            }
            for (int e = 0; e < cnt; e++) {
                float nrm = __shfl_sync(0xffffffffu, nrm_l, e);
                int sl = __shfl_sync(0xffffffffu, sl_l, e);
                if (nrm != 0.f) {
                    float2 hv = *(const float2*)&hs[sl * 64 + 2 * lane];
                    acc0 += nrm * hv.x;
                    acc1 += nrm * hv.y;
                }
            }
        }
        float sw = md * dd * dd;
        float2 hd = *(const float2*)&hs[d * 64 + 2 * lane];
        float o0 = fmaxf(acc0 + sw * hd.x + b0, 0.f);
        float o1 = fmaxf(acc1 + sw * hd.y + b1, 0.f);
        *(float2*)&d_X[(gbase + d) * FD + f0 + 2 * lane] = make_float2(o0, o1);
    }
}

// ---------------- pooling score ----------------
__global__ void k_score(const float* __restrict__ p) {
    int gw = (blockIdx.x * blockDim.x + threadIdx.x) >> 5;
    int lane = threadIdx.x & 31;
    if (gw >= NN) return;
    const float* xr = d_X + gw * FD;
    float s1 = 0.f, s2 = 0.f;
#pragma unroll
    for (int f = lane; f < FD; f += 32) {
        float pv = p[f];
        s1 += xr[f] * pv;
        s2 += pv * pv;
    }
#pragma unroll
    for (int o = 16; o > 0; o >>= 1) {
        s1 += __shfl_down_sync(0xffffffffu, s1, o);
        s2 += __shfl_down_sync(0xffffffffu, s2, o);
    }
    if (lane == 0) {
        float z = s1 / sqrtf(s2);
        d_score[gw] = 1.f / (1.f + expf(-z));
    }
}

// ---------------- per-graph top-k (bitonic, jax tie-break) + gate + mask + alive list ----
__global__ void __launch_bounds__(256) k_topk(int k) {
    __shared__ unsigned long long keys[512];
    __shared__ float gate[512];
    int g = blockIdx.x, tid = threadIdx.x;
    int gbase = g * NPG;

    for (int i = tid; i < 512; i += 256) {
        float m = d_mask[gbase + i];
        float sc = d_score[gbase + i];
        unsigned int bs = __float_as_uint(sc);
        unsigned int u = (bs & 0x80000000u) ? ~bs : (bs | 0x80000000u);
        if (m == 0.f) u = 0u;
        keys[i] = ((unsigned long long)u << 32) | (unsigned int)(511 - i);
        gate[i] = 0.f;
    }
    __syncthreads();

    for (int ksz = 2; ksz <= 512; ksz <<= 1) {
        for (int j = ksz >> 1; j > 0; j >>= 1) {
            for (int t = tid; t < 512; t += 256) {
                int ixj = t ^ j;
                if (ixj > t) {
                    bool asc = (t & ksz) != 0;
                    unsigned long long a = keys[t], b = keys[ixj];
                    if ((a > b) == asc) { keys[t] = b; keys[ixj] = a; }
                }
            }
            __syncthreads();
        }
    }

    if (tid < k) {
        int i = 511 - (int)(keys[tid] & 0xFFFFFFFFull);
        gate[i] = d_score[gbase + i];
        d_alive[g * k + tid] = gbase + i;
    }
    __syncthreads();

    for (int i = tid; i < 512; i += 256)
        d_mask[gbase + i] = (gate[i] > 0.f) ? 1.f : 0.f;
    for (int idx = tid; idx < 512 * FD; idx += 256) {
        int i = idx >> 7;
        d_X[gbase * FD + idx] *= gate[i];
    }
}

// ---------------- readout (max ++ mean, relu-accumulated into hg) ----------------
__global__ void k_readout() {
    int g = blockIdx.x, f = threadIdx.x;  // 128 threads
    int gbase = g * NPG;
    float mx = -1e30f, sm = 0.f, ct = 0.f;
    for (int n = 0; n < NPG; n++) {
        float m = d_mask[gbase + n];
        if (m > 0.f) {
            float v = d_X[(gbase + n) * FD + f];
            mx = fmaxf(mx, v);
            sm += v;
            ct += 1.f;
        }
    }
    float avg = sm / fmaxf(ct, 1.f);
    d_hg[g * 256 + f]       += fmaxf(mx, 0.f);
    d_hg[g * 256 + 128 + f] += fmaxf(avg, 0.f);
}

// ---------------- fused MLP head ----------------
__global__ void __launch_bounds__(256) k_head(const float* __restrict__ inp_c,
                                              const float* __restrict__ We,
                                              const float* __restrict__ Wa,
                                              const float* __restrict__ ba,
                                              const float* __restrict__ Wb,
                                              const float* __restrict__ bb,
                                              const float* __restrict__ Wc,
                                              float* __restrict__ out) {
    __shared__ float fu[320];
    __shared__ float h1[256];
    __shared__ float h2[128];
    __shared__ float red[128];
    int g = blockIdx.x, tid = threadIdx.x;

    if (tid < 64) {
        float a = 0.f;
        for (int i = 0; i < 64; i++) a += inp_c[g * 64 + i] * We[i * 64 + tid];
        fu[tid] = fmaxf(a, 0.f);
    }
    fu[64 + tid] = d_hg[g * 256 + tid];
    __syncthreads();

    float a = ba[tid];
    for (int i = 0; i < 320; i++) a += fu[i] * Wa[i * 256 + tid];
    h1[tid] = fmaxf(a, 0.f);
    __syncthreads();

    if (tid < 128) {
        float c = bb[tid];
        for (int i = 0; i < 256; i++) c += h1[i] * Wb[i * 128 + tid];
        h2[tid] = fmaxf(c, 0.f);
    }
    __syncthreads();

    if (tid < 128) red[tid] = h2[tid] * Wc[tid];
    __syncthreads();
    for (int o = 64; o > 0; o >>= 1) {
        if (tid < o) red[tid] += red[tid + o];
        __syncthreads();
    }
    if (tid == 0) out[g] = red[0];
}

// ---------------- launch ----------------
extern "C" void kernel_launch(void* const* d_in, const int* in_sizes, int n_in,
                              void* d_out, int out_size) {
    const float* x     = (const float*)d_in[0];
    const float* inp_c = (const float*)d_in[1];
    const int*   ei    = (const int*)d_in[2];
    const int*   src   = ei;
    const int*   dst   = ei + EE;
    const float* W1 = (const float*)d_in[4];
    const float* b1 = (const float*)d_in[5];
    const float* W2 = (const float*)d_in[6];
    const float* b2 = (const float*)d_in[7];
    const float* W3 = (const float*)d_in[8];
    const float* b3 = (const float*)d_in[9];
    const float* p1 = (const float*)d_in[10];
    const float* p2 = (const float*)d_in[11];
    const float* p3 = (const float*)d_in[12];
    const float* We = (const float*)d_in[13];
    const float* Wa = (const float*)d_in[14];
    const float* ba = (const float*)d_in[15];
    const float* Wb = (const float*)d_in[16];
    const float* bb = (const float*)d_in[17];
    const float* Wc = (const float*)d_in[18];
    float* out = (float*)d_out;

    cudaFuncSetAttribute((const void*)k_agg,
                         cudaFuncAttributeMaxDynamicSharedMemorySize, 131072);
    size_t aggsm = 512 * 64 * sizeof(float);

    k_init<<<256, 256>>>();
    k_count<<<EE / 256, 256>>>(dst);
    k_scan<<<1, 1024>>>();
    k_fill<<<EE / 256, 256>>>(src, dst);

    // ---- layer 1 (x is [NN, 128]: GID=128!) ----
    k_deg<<<NN / 256, 256>>>();
    k_gemm<128, false, false><<<NN / 64, 256>>>(x, W1);
    k_agg<<<dim3(NB, 2), 512, aggsm>>>(b1);
    k_score<<<NN / 8, 256>>>(p1);
    k_topk<<<NB, 256>>>(256);
    k_readout<<<NB, 128>>>();

    // ---- layer 2 (32768 alive rows) ----
    k_deg<<<NN / 256, 256>>>();
    k_gemm<128, true, true><<<(NB * 256) / 64, 256>>>(nullptr, W2);
    k_agg<<<dim3(NB, 2), 512, aggsm>>>(b2);
    k_score<<<NN / 8, 256>>>(p2);
    k_topk<<<NB, 256>>>(128);
    k_readout<<<NB, 128>>>();

    // ---- layer 3 (16384 alive rows) ----
    k_deg<<<NN / 256, 256>>>();
    k_gemm<128, true, true><<<(NB * 128) / 64, 256>>>(nullptr, W3);
    k_agg<<<dim3(NB, 2), 512, aggsm>>>(b3);
    k_score<<<NN / 8, 256>>>(p3);
    k_topk<<<NB, 256>>>(64);
    k_readout<<<NB, 128>>>();

    // ---- head ----
    k_head<<<NB, 256>>>(inp_c, We, Wa, ba, Wb, bb, Wc, out);
}

// round 3
// speedup vs baseline: 1.2554x; 1.2554x over previous
#include <cuda_runtime.h>

#define NN 65536      // total nodes
#define EE 1048576    // total edges
#define NB 128        // graphs
#define NPG 512       // nodes per graph
#define EPG 8192      // edges per graph (N*DEG)
#define FD 128        // feature dim

// ---------------- device scratch ----------------
__device__ __align__(256) float d_X[NN * FD];
__device__ __align__(256) float d_H[NN * FD];
__device__ __align__(256) float d_mask[NN];
__device__ __align__(256) float d_score[NN];
__device__ __align__(256) float d_sraw[NN];
__device__ __align__(256) unsigned short d_csr16[EE];
__device__ __align__(256) unsigned short d_goff[NB * (NPG + 1)];
__device__ __align__(256) int   d_alive[NB * 256];
__device__ __align__(256) float d_hg[NB * 256];

// ---------------- init ----------------
__global__ void k_init() {
    int i = blockIdx.x * blockDim.x + threadIdx.x;
    int stride = gridDim.x * blockDim.x;
    for (int j = i; j < NN; j += stride) { d_mask[j] = 1.f; d_sraw[j] = 0.f; }
    for (int j = i; j < NB * 256; j += stride) d_hg[j] = 0.f;
}

// ---------------- per-graph CSR build, all in smem ----------------
__global__ void __launch_bounds__(512) k_csr(const int* __restrict__ src,
                                             const int* __restrict__ dst) {
    __shared__ unsigned short s_src[EPG];
    __shared__ unsigned short s_dst[EPG];
    __shared__ int cnt[NPG];
    __shared__ int scn[NPG];
    __shared__ int cur[NPG];
    int g = blockIdx.x, tid = threadIdx.x;
    int gb = g * NPG, eb = g * EPG;

    cnt[tid] = 0;
    for (int e = tid; e < EPG; e += 512) {
        s_src[e] = (unsigned short)(src[eb + e] - gb);
        s_dst[e] = (unsigned short)(dst[eb + e] - gb);
    }
    __syncthreads();
    for (int e = tid; e < EPG; e += 512) atomicAdd(&cnt[s_dst[e]], 1);
    __syncthreads();
    // inclusive scan over 512 counters
    scn[tid] = cnt[tid];
    __syncthreads();
    for (int o = 1; o < 512; o <<= 1) {
        int a = scn[tid];
        int b = (tid >= o) ? scn[tid - o] : 0;
        __syncthreads();
        scn[tid] = a + b;
        __syncthreads();
    }
    int excl = scn[tid] - cnt[tid];
    cur[tid] = excl;
    d_goff[g * (NPG + 1) + tid] = (unsigned short)excl;
    if (tid == 511) d_goff[g * (NPG + 1) + NPG] = (unsigned short)EPG;
    __syncthreads();
    for (int e = tid; e < EPG; e += 512) {
        int d = s_dst[e];
        int pos = atomicAdd(&cur[d], 1);
        d_csr16[eb + pos] = s_src[e];
    }
}

// ---------------- GEMM: H[rows] = gate*A[rows] @ W (128x128x8, dbl-buffered) ----------
template <bool USEIDX, bool GATE>
__global__ void __launch_bounds__(256) k_gemm(const float* __restrict__ Ain,
                                              const float* __restrict__ W) {
    __shared__ float As[2][8][128];
    __shared__ float Bs[2][8][128];
    const int tid = threadIdx.x;
    const int rowBase = blockIdx.x * 128;

    const int a_r = tid >> 1;
    const int a_k = (tid & 1) * 4;
    int grow = USEIDX ? d_alive[rowBase + a_r] : (rowBase + a_r);
    float gate = 1.f;
    if (GATE) gate = d_score[grow];
    const float* Arow = (USEIDX ? (const float*)d_X : Ain) + (size_t)grow * FD;

    const int b_k = tid >> 5;
    const int b_n = (tid & 31) * 4;
    const int c0 = (tid & 15) * 8;
    const int r0 = (tid >> 4) * 8;

    // prologue: tile 0
    float4 av = *(const float4*)&Arow[a_k];
    float4 bv = *(const float4*)&W[b_k * FD + b_n];
    if (GATE) { av.x *= gate; av.y *= gate; av.z *= gate; av.w *= gate; }
    As[0][a_k + 0][a_r] = av.x;
    As[0][a_k + 1][a_r] = av.y;
    As[0][a_k + 2][a_r] = av.z;
    As[0][a_k + 3][a_r] = av.w;
    *(float4*)&Bs[0][b_k][b_n] = bv;
    __syncthreads();
    // preload tile 1
    av = *(const float4*)&Arow[8 + a_k];
    bv = *(const float4*)&W[(8 + b_k) * FD + b_n];
    if (GATE) { av.x *= gate; av.y *= gate; av.z *= gate; av.w *= gate; }

    float acc[8][8] = {};
#pragma unroll 1
    for (int it = 0; it < 16; it++) {
        const int buf = it & 1;
#pragma unroll
        for (int kk = 0; kk < 8; kk++) {
            float a0[8], b0[8];
            *(float4*)&a0[0] = *(float4*)&As[buf][kk][r0];
            *(float4*)&a0[4] = *(float4*)&As[buf][kk][r0 + 4];
            *(float4*)&b0[0] = *(float4*)&Bs[buf][kk][c0];
            *(float4*)&b0[4] = *(float4*)&Bs[buf][kk][c0 + 4];
#pragma unroll
            for (int i = 0; i < 8; i++)
#pragma unroll
                for (int j = 0; j < 8; j++) acc[i][j] += a0[i] * b0[j];
        }
        if (it < 15) {
            const int nb = buf ^ 1;
            As[nb][a_k + 0][a_r] = av.x;
            As[nb][a_k + 1][a_r] = av.y;
            As[nb][a_k + 2][a_r] = av.z;
            As[nb][a_k + 3][a_r] = av.w;
            *(float4*)&Bs[nb][b_k][b_n] = bv;
            __syncthreads();
            if (it < 14) {
                int k0 = (it + 2) * 8;
                av = *(const float4*)&Arow[k0 + a_k];
                bv = *(const float4*)&W[(k0 + b_k) * FD + b_n];
                if (GATE) { av.x *= gate; av.y *= gate; av.z *= gate; av.w *= gate; }
            }
        }
    }
#pragma unroll
    for (int i = 0; i < 8; i++) {
        int orow = USEIDX ? d_alive[rowBase + r0 + i] : (rowBase + r0 + i);
        *(float4*)&d_H[(size_t)orow * FD + c0] =
            make_float4(acc[i][0], acc[i][1], acc[i][2], acc[i][3]);
        *(float4*)&d_H[(size_t)orow * FD + c0 + 4] =
            make_float4(acc[i][4], acc[i][5], acc[i][6], acc[i][7]);
    }
}

// ---------------- GCN agg: fused dinv + self-loop + bias + relu + pool-score dot ------
// grid (NB, 2): graph g, feature half hf. 512 threads. 128KB dyn smem.
__global__ void __launch_bounds__(512) k_agg(const float* __restrict__ bias,
                                             const float* __restrict__ p) {
    extern __shared__ float hs[];                    // [512][64]
    __shared__ __align__(16) unsigned short csr_s[EPG];
    __shared__ unsigned short off_s[NPG + 1];
    __shared__ float mask_s[NPG], dinv_s[NPG];

    int g = blockIdx.x, hf = blockIdx.y;
    int f0 = hf * 64;
    int tid = threadIdx.x;
    int gbase = g * NPG;

    // phase 1: mask, offsets, csr
    mask_s[tid] = d_mask[gbase + tid];
    for (int i = tid; i < NPG + 1; i += 512) off_s[i] = d_goff[g * (NPG + 1) + i];
    {
        const uint4* gp = (const uint4*)(d_csr16 + g * EPG);
        uint4* sp = (uint4*)csr_s;
        for (int j = tid; j < EPG / 8; j += 512) sp[j] = gp[j];
    }
    __syncthreads();

    // phase 2: dinv + H tile load (alive rows only)
    {
        int e0 = off_s[tid], e1 = off_s[tid + 1];
        float s = 0.f;
        for (int e = e0; e < e1; e++) s += mask_s[csr_s[e]];
        float deg = mask_s[tid] * (1.f + s);
        dinv_s[tid] = rsqrtf(fmaxf(deg, 1.f));
    }
    for (int idx4 = tid; idx4 < 512 * 16; idx4 += 512) {
        int row = idx4 >> 4, c4 = idx4 & 15;
        if (mask_s[row] != 0.f)
            *(float4*)&hs[row * 64 + c4 * 4] =
                *(const float4*)&d_H[(size_t)(gbase + row) * FD + f0 + c4 * 4];
    }
    __syncthreads();

    int w = tid >> 5, lane = tid & 31;
    float b0 = bias[f0 + 2 * lane], b1 = bias[f0 + 2 * lane + 1];
    float p0 = p[f0 + 2 * lane], p1 = p[f0 + 2 * lane + 1];

    for (int it = 0; it < 32; it++) {
        int d = w + it * 16;
        float md = mask_s[d];
        if (md == 0.f) continue;
        float dd = dinv_s[d];
        int e0 = off_s[d], e1 = off_s[d + 1];
        float acc0 = 0.f, acc1 = 0.f;
        for (int base = e0; base < e1; base += 32) {
            int cnt = min(32, e1 - base);
            int sl_l = 0;
            float nrm_l = 0.f;
            if (lane < cnt) {
                sl_l = csr_s[base + lane];
                nrm_l = mask_s[sl_l] * dd * dinv_s[sl_l];
            }
            for (int e = 0; e < cnt; e++) {
                float nrm = __shfl_sync(0xffffffffu, nrm_l, e);
                int sl = __shfl_sync(0xffffffffu, sl_l, e);
                if (nrm != 0.f) {
                    float2 hv = *(const float2*)&hs[sl * 64 + 2 * lane];
                    acc0 += nrm * hv.x;
                    acc1 += nrm * hv.y;
                }
            }
        }
        float sw = md * dd * dd;
        float2 hd = *(const float2*)&hs[d * 64 + 2 * lane];
        float o0 = fmaxf(acc0 + sw * hd.x + b0, 0.f);
        float o1 = fmaxf(acc1 + sw * hd.y + b1, 0.f);
        *(float2*)&d_X[(size_t)(gbase + d) * FD + f0 + 2 * lane] = make_float2(o0, o1);
        // fused pool-score partial dot (64 of 128 features)
        float part = o0 * p0 + o1 * p1;
#pragma unroll
        for (int o = 16; o > 0; o >>= 1)
            part += __shfl_down_sync(0xffffffffu, part, o);
        if (lane == 0) atomicAdd(&d_sraw[gbase + d], part);
    }
}

// ---------------- per-graph top-k: sigmoid + bitonic + mask + alive list --------------
__global__ void __launch_bounds__(256) k_topk(int k, const float* __restrict__ p) {
    __shared__ unsigned long long keys[NPG];
    __shared__ float gate[NPG];
    __shared__ float pp[128];
    int g = blockIdx.x, tid = threadIdx.x;
    int gbase = g * NPG;

    if (tid < 128) { float v = p[tid]; pp[tid] = v * v; }
    __syncthreads();
    for (int o = 64; o > 0; o >>= 1) {
        if (tid < o) pp[tid] += pp[tid + o];
        __syncthreads();
    }
    float pinv = rsqrtf(pp[0]);

    for (int i = tid; i < NPG; i += 256) {
        float m = d_mask[gbase + i];
        float raw = d_sraw[gbase + i];
        d_sraw[gbase + i] = 0.f;                     // reset for next layer
        float sc = 1.f / (1.f + expf(-raw * pinv));
        d_score[gbase + i] = sc;
        unsigned int bs = __float_as_uint(sc);
        unsigned int u = (bs & 0x80000000u) ? ~bs : (bs | 0x80000000u);
        if (m == 0.f) u = 0u;
        keys[i] = ((unsigned long long)u << 32) | (unsigned int)(511 - i);
        gate[i] = 0.f;
    }
    __syncthreads();

    for (int ksz = 2; ksz <= NPG; ksz <<= 1) {
        for (int j = ksz >> 1; j > 0; j >>= 1) {
            for (int t = tid; t < NPG; t += 256) {
                int ixj = t ^ j;
                if (ixj > t) {
                    bool asc = (t & ksz) != 0;
                    unsigned long long a = keys[t], b = keys[ixj];
                    if ((a > b) == asc) { keys[t] = b; keys[ixj] = a; }
                }
            }
            __syncthreads();
        }
    }

    if (tid < k) {
        int i = 511 - (int)(keys[tid] & 0xFFFFFFFFull);
        gate[i] = 1.f;
        d_alive[g * k + tid] = gbase + i;
    }
    __syncthreads();
    for (int i = tid; i < NPG; i += 256)
        d_mask[gbase + i] = gate[i];
}

// ---------------- readout: max ++ mean of (x * score) over alive, relu-accumulated ----
__global__ void __launch_bounds__(512) k_readout(int kcnt) {
    __shared__ float smx[4][128], ssm[4][128];
    int g = blockIdx.x, tid = threadIdx.x;
    int f = tid & 127, seg = tid >> 7;
    int gb = g * NPG;
    float mx = -1e30f, sm = 0.f;
    for (int n = seg * 128; n < seg * 128 + 128; n++) {
        if (d_mask[gb + n] > 0.f) {
            float v = d_X[(size_t)(gb + n) * FD + f] * d_score[gb + n];
            mx = fmaxf(mx, v);
            sm += v;
        }
    }
    smx[seg][f] = mx;
    ssm[seg][f] = sm;
    __syncthreads();
    if (seg == 0) {
#pragma unroll
        for (int s = 1; s < 4; s++) {
            mx = fmaxf(mx, smx[s][f]);
            sm += ssm[s][f];
        }
        d_hg[g * 256 + f]       += fmaxf(mx, 0.f);
        d_hg[g * 256 + 128 + f] += fmaxf(sm / (float)kcnt, 0.f);
    }
}

// ---------------- fused MLP head ----------------
__global__ void __launch_bounds__(256) k_head(const float* __restrict__ inp_c,
                                              const float* __restrict__ We,
                                              const float* __restrict__ Wa,
                                              const float* __restrict__ ba,
                                              const float* __restrict__ Wb,
                                              const float* __restrict__ bb,
                                              const float* __restrict__ Wc,
                                              float* __restrict__ out) {
    __shared__ float fu[320];
    __shared__ float h1[256];
    __shared__ float h2[128];
    __shared__ float red[128];
    int g = blockIdx.x, tid = threadIdx.x;

    if (tid < 64) {
        float a = 0.f;
        for (int i = 0; i < 64; i++) a += inp_c[g * 64 + i] * We[i * 64 + tid];
        fu[tid] = fmaxf(a, 0.f);
    }
    fu[64 + tid] = d_hg[g * 256 + tid];
    __syncthreads();

    float a = ba[tid];
    for (int i = 0; i < 320; i++) a += fu[i] * Wa[i * 256 + tid];
    h1[tid] = fmaxf(a, 0.f);
    __syncthreads();

    if (tid < 128) {
        float c = bb[tid];
        for (int i = 0; i < 256; i++) c += h1[i] * Wb[i * 128 + tid];
        h2[tid] = fmaxf(c, 0.f);
    }
    __syncthreads();

    if (tid < 128) red[tid] = h2[tid] * Wc[tid];
    __syncthreads();
    for (int o = 64; o > 0; o >>= 1) {
        if (tid < o) red[tid] += red[tid + o];
        __syncthreads();
    }
    if (tid == 0) out[g] = red[0];
}

// ---------------- launch ----------------
extern "C" void kernel_launch(void* const* d_in, const int* in_sizes, int n_in,
                              void* d_out, int out_size) {
    const float* x     = (const float*)d_in[0];
    const float* inp_c = (const float*)d_in[1];
    const int*   ei    = (const int*)d_in[2];
    const int*   src   = ei;
    const int*   dst   = ei + EE;
    const float* W1 = (const float*)d_in[4];
    const float* b1 = (const float*)d_in[5];
    const float* W2 = (const float*)d_in[6];
    const float* b2 = (const float*)d_in[7];
    const float* W3 = (const float*)d_in[8];
    const float* b3 = (const float*)d_in[9];
    const float* p1 = (const float*)d_in[10];
    const float* p2 = (const float*)d_in[11];
    const float* p3 = (const float*)d_in[12];
    const float* We = (const float*)d_in[13];
    const float* Wa = (const float*)d_in[14];
    const float* ba = (const float*)d_in[15];
    const float* Wb = (const float*)d_in[16];
    const float* bb = (const float*)d_in[17];
    const float* Wc = (const float*)d_in[18];
    float* out = (float*)d_out;

    cudaFuncSetAttribute((const void*)k_agg,
                         cudaFuncAttributeMaxDynamicSharedMemorySize, 131072);
    size_t aggsm = 512 * 64 * sizeof(float);

    k_init<<<128, 256>>>();
    k_csr<<<NB, 512>>>(src, dst);

    // ---- layer 1 ----
    k_gemm<false, false><<<NN / 128, 256>>>(x, W1);
    k_agg<<<dim3(NB, 2), 512, aggsm>>>(b1, p1);
    k_topk<<<NB, 256>>>(256, p1);
    k_readout<<<NB, 512>>>(256);

    // ---- layer 2 (32768 alive rows, gated A) ----
    k_gemm<true, true><<<(NB * 256) / 128, 256>>>(nullptr, W2);
    k_agg<<<dim3(NB, 2), 512, aggsm>>>(b2, p2);
    k_topk<<<NB, 256>>>(128, p2);
    k_readout<<<NB, 512>>>(128);

    // ---- layer 3 (16384 alive rows, gated A) ----
    k_gemm<true, true><<<(NB * 128) / 128, 256>>>(nullptr, W3);
    k_agg<<<dim3(NB, 2), 512, aggsm>>>(b3, p3);
    k_topk<<<NB, 256>>>(64, p3);
    k_readout<<<NB, 512>>>(64);

    // ---- head ----
    k_head<<<NB, 256>>>(inp_c, We, Wa, ba, Wb, bb, Wc, out);
}

// round 4
// speedup vs baseline: 1.6740x; 1.3334x over previous
#include <cuda_runtime.h>

#define NN 65536      // total nodes
#define EE 1048576    // total edges
#define NB 128        // graphs
#define NPG 512       // nodes per graph
#define EPG 8192      // edges per graph (N*DEG)
#define FD 128        // feature dim

// ---------------- device scratch ----------------
__device__ __align__(256) float d_X[NN * FD];
__device__ __align__(256) float d_H[NN * FD];
__device__ __align__(256) float d_mask[NN];
__device__ __align__(256) float d_score[NN];
__device__ __align__(256) float d_sraw[NN];
__device__ __align__(256) unsigned short d_csr16[EE];
__device__ __align__(256) unsigned short d_goff[NB * (NPG + 1)];
__device__ __align__(256) int   d_alive[NB * 256];
__device__ __align__(256) float d_hg[NB * 256];

// ---------------- init ----------------
__global__ void k_init() {
    int i = blockIdx.x * blockDim.x + threadIdx.x;
    int stride = gridDim.x * blockDim.x;
    for (int j = i; j < NN; j += stride) { d_mask[j] = 1.f; d_sraw[j] = 0.f; }
    for (int j = i; j < NB * 256; j += stride) d_hg[j] = 0.f;
}

// ---------------- per-graph CSR build, all in smem ----------------
__global__ void __launch_bounds__(512) k_csr(const int* __restrict__ src,
                                             const int* __restrict__ dst) {
    __shared__ unsigned short s_src[EPG];
    __shared__ unsigned short s_dst[EPG];
    __shared__ int cnt[NPG];
    __shared__ int scn[NPG];
    __shared__ int cur[NPG];
    int g = blockIdx.x, tid = threadIdx.x;
    int gb = g * NPG, eb = g * EPG;

    cnt[tid] = 0;
    for (int e = tid; e < EPG; e += 512) {
        s_src[e] = (unsigned short)(src[eb + e] - gb);
        s_dst[e] = (unsigned short)(dst[eb + e] - gb);
    }
    __syncthreads();
    for (int e = tid; e < EPG; e += 512) atomicAdd(&cnt[s_dst[e]], 1);
    __syncthreads();
    scn[tid] = cnt[tid];
    __syncthreads();
    for (int o = 1; o < 512; o <<= 1) {
        int a = scn[tid];
        int b = (tid >= o) ? scn[tid - o] : 0;
        __syncthreads();
        scn[tid] = a + b;
        __syncthreads();
    }
    int excl = scn[tid] - cnt[tid];
    cur[tid] = excl;
    d_goff[g * (NPG + 1) + tid] = (unsigned short)excl;
    if (tid == 511) d_goff[g * (NPG + 1) + NPG] = (unsigned short)EPG;
    __syncthreads();
    for (int e = tid; e < EPG; e += 512) {
        int d = s_dst[e];
        int pos = atomicAdd(&cur[d], 1);
        d_csr16[eb + pos] = s_src[e];
    }
}

// ---------------- GEMM: H[rows] = gate*A[rows] @ W (128x128x8, dbl-buffered) ----------
template <bool USEIDX, bool GATE>
__global__ void __launch_bounds__(256) k_gemm(const float* __restrict__ Ain,
                                              const float* __restrict__ W) {
    __shared__ float As[2][8][128];
    __shared__ float Bs[2][8][128];
    const int tid = threadIdx.x;
    const int rowBase = blockIdx.x * 128;

    const int a_r = tid >> 1;
    const int a_k = (tid & 1) * 4;
    int grow = USEIDX ? d_alive[rowBase + a_r] : (rowBase + a_r);
    float gate = 1.f;
    if (GATE) gate = d_score[grow];
    const float* Arow = (USEIDX ? (const float*)d_X : Ain) + (size_t)grow * FD;

    const int b_k = tid >> 5;
    const int b_n = (tid & 31) * 4;
    const int c0 = (tid & 15) * 8;
    const int r0 = (tid >> 4) * 8;

    float4 av = *(const float4*)&Arow[a_k];
    float4 bv = *(const float4*)&W[b_k * FD + b_n];
    if (GATE) { av.x *= gate; av.y *= gate; av.z *= gate; av.w *= gate; }
    As[0][a_k + 0][a_r] = av.x;
    As[0][a_k + 1][a_r] = av.y;
    As[0][a_k + 2][a_r] = av.z;
    As[0][a_k + 3][a_r] = av.w;
    *(float4*)&Bs[0][b_k][b_n] = bv;
    __syncthreads();
    av = *(const float4*)&Arow[8 + a_k];
    bv = *(const float4*)&W[(8 + b_k) * FD + b_n];
    if (GATE) { av.x *= gate; av.y *= gate; av.z *= gate; av.w *= gate; }

    float acc[8][8] = {};
#pragma unroll 1
    for (int it = 0; it < 16; it++) {
        const int buf = it & 1;
#pragma unroll
        for (int kk = 0; kk < 8; kk++) {
            float a0[8], b0[8];
            *(float4*)&a0[0] = *(float4*)&As[buf][kk][r0];
            *(float4*)&a0[4] = *(float4*)&As[buf][kk][r0 + 4];
            *(float4*)&b0[0] = *(float4*)&Bs[buf][kk][c0];
            *(float4*)&b0[4] = *(float4*)&Bs[buf][kk][c0 + 4];
#pragma unroll
            for (int i = 0; i < 8; i++)
#pragma unroll
                for (int j = 0; j < 8; j++) acc[i][j] += a0[i] * b0[j];
        }
        if (it < 15) {
            const int nb = buf ^ 1;
            As[nb][a_k + 0][a_r] = av.x;
            As[nb][a_k + 1][a_r] = av.y;
            As[nb][a_k + 2][a_r] = av.z;
            As[nb][a_k + 3][a_r] = av.w;
            *(float4*)&Bs[nb][b_k][b_n] = bv;
            __syncthreads();
            if (it < 14) {
                int k0 = (it + 2) * 8;
                av = *(const float4*)&Arow[k0 + a_k];
                bv = *(const float4*)&W[(k0 + b_k) * FD + b_n];
                if (GATE) { av.x *= gate; av.y *= gate; av.z *= gate; av.w *= gate; }
            }
        }
    }
#pragma unroll
    for (int i = 0; i < 8; i++) {
        int orow = USEIDX ? d_alive[rowBase + r0 + i] : (rowBase + r0 + i);
        *(float4*)&d_H[(size_t)orow * FD + c0] =
            make_float4(acc[i][0], acc[i][1], acc[i][2], acc[i][3]);
        *(float4*)&d_H[(size_t)orow * FD + c0 + 4] =
            make_float4(acc[i][4], acc[i][5], acc[i][6], acc[i][7]);
    }
}

// ---------------- GCN agg: factored norms, no shuffles ----------------
// norm(s,d) = dinvm[s] * dinvm[d], dinvm[i] = mask[i]*dinv[i].
// acc_d = sum_e dinvm[src_e] * h[src_e];  out = mask_d*relu(dinv_d*mask_d*acc... )
// grid (NB, 2): graph g, feature half hf. 512 threads. 128KB dyn smem.
__global__ void __launch_bounds__(512) k_agg(const float* __restrict__ bias,
                                             const float* __restrict__ p) {
    extern __shared__ float hs[];                    // [512][64]
    __shared__ __align__(16) unsigned short csr_s[EPG];
    __shared__ unsigned short off_s[NPG + 1];
    __shared__ float mask_s[NPG], dinv_s[NPG], dinvm_s[NPG];

    int g = blockIdx.x, hf = blockIdx.y;
    int f0 = hf * 64;
    int tid = threadIdx.x;
    int gbase = g * NPG;

    // phase 1: mask, offsets, csr, H tile (unconditional)
    mask_s[tid] = d_mask[gbase + tid];
    for (int i = tid; i < NPG + 1; i += 512) off_s[i] = d_goff[g * (NPG + 1) + i];
    {
        const uint4* gp = (const uint4*)(d_csr16 + g * EPG);
        uint4* sp = (uint4*)csr_s;
        for (int j = tid; j < EPG / 8; j += 512) sp[j] = gp[j];
    }
    for (int idx4 = tid; idx4 < 512 * 16; idx4 += 512) {
        int row = idx4 >> 4, c4 = idx4 & 15;
        *(float4*)&hs[row * 64 + c4 * 4] =
            *(const float4*)&d_H[(size_t)(gbase + row) * FD + f0 + c4 * 4];
    }
    __syncthreads();

    // phase 2: dinv / dinvm per row
    {
        int e0 = off_s[tid], e1 = off_s[tid + 1];
        float s = 0.f;
        for (int e = e0; e < e1; e++) s += mask_s[csr_s[e]];
        float m = mask_s[tid];
        float deg = m * (1.f + s);
        float dv = rsqrtf(fmaxf(deg, 1.f));
        dinv_s[tid] = dv;
        dinvm_s[tid] = m * dv;
    }
    __syncthreads();

    int w = tid >> 5, lane = tid & 31;
    float b0 = bias[f0 + 2 * lane], b1 = bias[f0 + 2 * lane + 1];
    float p0 = p[f0 + 2 * lane], p1 = p[f0 + 2 * lane + 1];

#pragma unroll 1
    for (int it = 0; it < 32; it++) {
        int d = (w << 5) + it;                      // contiguous rows per warp
        float md = mask_s[d];
        if (md == 0.f) continue;                     // dead dst: nothing downstream reads it
        float dv = dinv_s[d];
        int e0 = off_s[d], e1 = off_s[d + 1];
        float acc0 = 0.f, acc1 = 0.f;
#pragma unroll 4
        for (int e = e0; e < e1; e++) {
            int sl = csr_s[e];                       // broadcast LDS.U16
            float nm = dinvm_s[sl];                  // broadcast LDS.F32
            float2 hv = *(const float2*)&hs[sl * 64 + 2 * lane];  // conflict-free LDS.64
            acc0 += nm * hv.x;
            acc1 += nm * hv.y;
        }
        float sw = dv * dv;                          // self-loop norm (md=1 here)
        float2 hd = *(const float2*)&hs[d * 64 + 2 * lane];
        float o0 = fmaxf(fmaf(dv, acc0, fmaf(sw, hd.x, b0)), 0.f);
        float o1 = fmaxf(fmaf(dv, acc1, fmaf(sw, hd.y, b1)), 0.f);
        *(float2*)&d_X[(size_t)(gbase + d) * FD + f0 + 2 * lane] = make_float2(o0, o1);
        // fused pool-score partial dot (this feature half)
        float part = o0 * p0 + o1 * p1;
#pragma unroll
        for (int o = 16; o > 0; o >>= 1)
            part += __shfl_down_sync(0xffffffffu, part, o);
        if (lane == 0) atomicAdd(&d_sraw[gbase + d], part);
    }
}

// ---------------- per-graph top-k: sigmoid + bitonic + mask + alive list --------------
__global__ void __launch_bounds__(256) k_topk(int k, const float* __restrict__ p) {
    __shared__ unsigned long long keys[NPG];
    __shared__ float gate[NPG];
    __shared__ float pp[128];
    int g = blockIdx.x, tid = threadIdx.x;
    int gbase = g * NPG;

    if (tid < 128) { float v = p[tid]; pp[tid] = v * v; }
    __syncthreads();
    for (int o = 64; o > 0; o >>= 1) {
        if (tid < o) pp[tid] += pp[tid + o];
        __syncthreads();
    }
    float pinv = rsqrtf(pp[0]);

    for (int i = tid; i < NPG; i += 256) {
        float m = d_mask[gbase + i];
        float raw = d_sraw[gbase + i];
        d_sraw[gbase + i] = 0.f;
        float sc = 1.f / (1.f + expf(-raw * pinv));
        d_score[gbase + i] = sc;
        unsigned int bs = __float_as_uint(sc);
        unsigned int u = (bs & 0x80000000u) ? ~bs : (bs | 0x80000000u);
        if (m == 0.f) u = 0u;
        keys[i] = ((unsigned long long)u << 32) | (unsigned int)(511 - i);
        gate[i] = 0.f;
    }
    __syncthreads();

    for (int ksz = 2; ksz <= NPG; ksz <<= 1) {
        for (int j = ksz >> 1; j > 0; j >>= 1) {
            for (int t = tid; t < NPG; t += 256) {
                int ixj = t ^ j;
                if (ixj > t) {
                    bool asc = (t & ksz) != 0;
                    unsigned long long a = keys[t], b = keys[ixj];
                    if ((a > b) == asc) { keys[t] = b; keys[ixj] = a; }
                }
            }
            __syncthreads();
        }
    }

    if (tid < k) {
        int i = 511 - (int)(keys[tid] & 0xFFFFFFFFull);
        gate[i] = 1.f;
        d_alive[g * k + tid] = gbase + i;
    }
    __syncthreads();
    for (int i = tid; i < NPG; i += 256)
        d_mask[gbase + i] = gate[i];
}

// ---------------- readout: max ++ mean of (x * score) over alive ----------------
__global__ void __launch_bounds__(512) k_readout(int kcnt) {
    __shared__ float smx[4][128], ssm[4][128];
    int g = blockIdx.x, tid = threadIdx.x;
    int f = tid & 127, seg = tid >> 7;
    int gb = g * NPG;
    float mx = -1e30f, sm = 0.f;
    for (int n = seg * 128; n < seg * 128 + 128; n++) {
        if (d_mask[gb + n] > 0.f) {
            float v = d_X[(size_t)(gb + n) * FD + f] * d_score[gb + n];
            mx = fmaxf(mx, v);
            sm += v;
        }
    }
    smx[seg][f] = mx;
    ssm[seg][f] = sm;
    __syncthreads();
    if (seg == 0) {
#pragma unroll
        for (int s = 1; s < 4; s++) {
            mx = fmaxf(mx, smx[s][f]);
            sm += ssm[s][f];
        }
        d_hg[g * 256 + f]       += fmaxf(mx, 0.f);
        d_hg[g * 256 + 128 + f] += fmaxf(sm / (float)kcnt, 0.f);
    }
}

// ---------------- fused MLP head ----------------
__global__ void __launch_bounds__(256) k_head(const float* __restrict__ inp_c,
                                              const float* __restrict__ We,
                                              const float* __restrict__ Wa,
                                              const float* __restrict__ ba,
                                              const float* __restrict__ Wb,
                                              const float* __restrict__ bb,
                                              const float* __restrict__ Wc,
                                              float* __restrict__ out) {
    __shared__ float fu[320];
    __shared__ float h1[256];
    __shared__ float h2[128];
    __shared__ float red[128];
    int g = blockIdx.x, tid = threadIdx.x;

    if (tid < 64) {
        float a = 0.f;
        for (int i = 0; i < 64; i++) a += inp_c[g * 64 + i] * We[i * 64 + tid];
        fu[tid] = fmaxf(a, 0.f);
    }
    fu[64 + tid] = d_hg[g * 256 + tid];
    __syncthreads();

    float a = ba[tid];
    for (int i = 0; i < 320; i++) a += fu[i] * Wa[i * 256 + tid];
    h1[tid] = fmaxf(a, 0.f);
    __syncthreads();

    if (tid < 128) {
        float c = bb[tid];
        for (int i = 0; i < 256; i++) c += h1[i] * Wb[i * 128 + tid];
        h2[tid] = fmaxf(c, 0.f);
    }
    __syncthreads();

    if (tid < 128) red[tid] = h2[tid] * Wc[tid];
    __syncthreads();
    for (int o = 64; o > 0; o >>= 1) {
        if (tid < o) red[tid] += red[tid + o];
        __syncthreads();
    }
    if (tid == 0) out[g] = red[0];
}

// ---------------- launch ----------------
extern "C" void kernel_launch(void* const* d_in, const int* in_sizes, int n_in,
                              void* d_out, int out_size) {
    const float* x     = (const float*)d_in[0];
    const float* inp_c = (const float*)d_in[1];
    const int*   ei    = (const int*)d_in[2];
    const int*   src   = ei;
    const int*   dst   = ei + EE;
    const float* W1 = (const float*)d_in[4];
    const float* b1 = (const float*)d_in[5];
    const float* W2 = (const float*)d_in[6];
    const float* b2 = (const float*)d_in[7];
    const float* W3 = (const float*)d_in[8];
    const float* b3 = (const float*)d_in[9];
    const float* p1 = (const float*)d_in[10];
    const float* p2 = (const float*)d_in[11];
    const float* p3 = (const float*)d_in[12];
    const float* We = (const float*)d_in[13];
    const float* Wa = (const float*)d_in[14];
    const float* ba = (const float*)d_in[15];
    const float* Wb = (const float*)d_in[16];
    const float* bb = (const float*)d_in[17];
    const float* Wc = (const float*)d_in[18];
    float* out = (float*)d_out;

    cudaFuncSetAttribute((const void*)k_agg,
                         cudaFuncAttributeMaxDynamicSharedMemorySize, 131072);
    size_t aggsm = 512 * 64 * sizeof(float);

    k_init<<<128, 256>>>();
    k_csr<<<NB, 512>>>(src, dst);

    // ---- layer 1 ----
    k_gemm<false, false><<<NN / 128, 256>>>(x, W1);
    k_agg<<<dim3(NB, 2), 512, aggsm>>>(b1, p1);
    k_topk<<<NB, 256>>>(256, p1);
    k_readout<<<NB, 512>>>(256);

    // ---- layer 2 (32768 alive rows, gated A) ----
    k_gemm<true, true><<<(NB * 256) / 128, 256>>>(nullptr, W2);
    k_agg<<<dim3(NB, 2), 512, aggsm>>>(b2, p2);
    k_topk<<<NB, 256>>>(128, p2);
    k_readout<<<NB, 512>>>(128);

    // ---- layer 3 (16384 alive rows, gated A) ----
    k_gemm<true, true><<<(NB * 128) / 128, 256>>>(nullptr, W3);
    k_agg<<<dim3(NB, 2), 512, aggsm>>>(b3, p3);
    k_topk<<<NB, 256>>>(64, p3);
    k_readout<<<NB, 512>>>(64);

    // ---- head ----
    k_head<<<NB, 256>>>(inp_c, We, Wa, ba, Wb, bb, Wc, out);
}

// round 5
// speedup vs baseline: 1.9091x; 1.1404x over previous
#include <cuda_runtime.h>

#define NN 65536      // total nodes
#define EE 1048576    // total edges
#define NB 128        // graphs
#define NPG 512       // nodes per graph
#define EPG 8192      // edges per graph (N*DEG)
#define FD 128        // feature dim

// ---------------- device scratch ----------------
__device__ __align__(256) float d_X[NN * FD];
__device__ __align__(256) float d_H[NN * FD];
__device__ __align__(256) float d_mask[NN];
__device__ __align__(256) float d_score[NN];
__device__ __align__(256) float d_sraw[NN];
__device__ __align__(256) unsigned short d_csr16[EE];
__device__ __align__(256) unsigned short d_goff[NB * (NPG + 1)];
__device__ __align__(256) int   d_alive[NB * 256];
__device__ __align__(256) float d_hg[NB * 256];

// ---------------- init ----------------
__global__ void k_init() {
    int i = blockIdx.x * blockDim.x + threadIdx.x;
    int stride = gridDim.x * blockDim.x;
    for (int j = i; j < NN; j += stride) { d_mask[j] = 1.f; d_sraw[j] = 0.f; }
    for (int j = i; j < NB * 256; j += stride) d_hg[j] = 0.f;
}

// ---------------- per-graph CSR build, all in smem ----------------
__global__ void __launch_bounds__(512) k_csr(const int* __restrict__ src,
                                             const int* __restrict__ dst) {
    __shared__ unsigned short s_src[EPG];
    __shared__ unsigned short s_dst[EPG];
    __shared__ int cnt[NPG];
    __shared__ int scn[NPG];
    __shared__ int cur[NPG];
    int g = blockIdx.x, tid = threadIdx.x;
    int gb = g * NPG, eb = g * EPG;

    cnt[tid] = 0;
    for (int e = tid; e < EPG; e += 512) {
        s_src[e] = (unsigned short)(src[eb + e] - gb);
        s_dst[e] = (unsigned short)(dst[eb + e] - gb);
    }
    __syncthreads();
    for (int e = tid; e < EPG; e += 512) atomicAdd(&cnt[s_dst[e]], 1);
    __syncthreads();
    scn[tid] = cnt[tid];
    __syncthreads();
    for (int o = 1; o < 512; o <<= 1) {
        int a = scn[tid];
        int b = (tid >= o) ? scn[tid - o] : 0;
        __syncthreads();
        scn[tid] = a + b;
        __syncthreads();
    }
    int excl = scn[tid] - cnt[tid];
    cur[tid] = excl;
    d_goff[g * (NPG + 1) + tid] = (unsigned short)excl;
    if (tid == 511) d_goff[g * (NPG + 1) + NPG] = (unsigned short)EPG;
    __syncthreads();
    for (int e = tid; e < EPG; e += 512) {
        int d = s_dst[e];
        int pos = atomicAdd(&cur[d], 1);
        d_csr16[eb + pos] = s_src[e];
    }
}

// ---------------- GEMM: H[rows] = gate*A[rows] @ W (128x128x8, dbl-buffered) ----------
template <bool USEIDX, bool GATE>
__global__ void __launch_bounds__(256) k_gemm(const float* __restrict__ Ain,
                                              const float* __restrict__ W) {
    __shared__ float As[2][8][128];
    __shared__ float Bs[2][8][128];
    const int tid = threadIdx.x;
    const int rowBase = blockIdx.x * 128;

    const int a_r = tid >> 1;
    const int a_k = (tid & 1) * 4;
    int grow = USEIDX ? d_alive[rowBase + a_r] : (rowBase + a_r);
    float gate = 1.f;
    if (GATE) gate = d_score[grow];
    const float* Arow = (USEIDX ? (const float*)d_X : Ain) + (size_t)grow * FD;

    const int b_k = tid >> 5;
    const int b_n = (tid & 31) * 4;
    const int c0 = (tid & 15) * 8;
    const int r0 = (tid >> 4) * 8;

    float4 av = *(const float4*)&Arow[a_k];
    float4 bv = *(const float4*)&W[b_k * FD + b_n];
    if (GATE) { av.x *= gate; av.y *= gate; av.z *= gate; av.w *= gate; }
    As[0][a_k + 0][a_r] = av.x;
    As[0][a_k + 1][a_r] = av.y;
    As[0][a_k + 2][a_r] = av.z;
    As[0][a_k + 3][a_r] = av.w;
    *(float4*)&Bs[0][b_k][b_n] = bv;
    __syncthreads();
    av = *(const float4*)&Arow[8 + a_k];
    bv = *(const float4*)&W[(8 + b_k) * FD + b_n];
    if (GATE) { av.x *= gate; av.y *= gate; av.z *= gate; av.w *= gate; }

    float acc[8][8] = {};
#pragma unroll 1
    for (int it = 0; it < 16; it++) {
        const int buf = it & 1;
#pragma unroll
        for (int kk = 0; kk < 8; kk++) {
            float a0[8], b0[8];
            *(float4*)&a0[0] = *(float4*)&As[buf][kk][r0];
            *(float4*)&a0[4] = *(float4*)&As[buf][kk][r0 + 4];
            *(float4*)&b0[0] = *(float4*)&Bs[buf][kk][c0];
            *(float4*)&b0[4] = *(float4*)&Bs[buf][kk][c0 + 4];
#pragma unroll
            for (int i = 0; i < 8; i++)
#pragma unroll
                for (int j = 0; j < 8; j++) acc[i][j] += a0[i] * b0[j];
        }
        if (it < 15) {
            const int nb = buf ^ 1;
            As[nb][a_k + 0][a_r] = av.x;
            As[nb][a_k + 1][a_r] = av.y;
            As[nb][a_k + 2][a_r] = av.z;
            As[nb][a_k + 3][a_r] = av.w;
            *(float4*)&Bs[nb][b_k][b_n] = bv;
            __syncthreads();
            if (it < 14) {
                int k0 = (it + 2) * 8;
                av = *(const float4*)&Arow[k0 + a_k];
                bv = *(const float4*)&W[(k0 + b_k) * FD + b_n];
                if (GATE) { av.x *= gate; av.y *= gate; av.z *= gate; av.w *= gate; }
            }
        }
    }
#pragma unroll
    for (int i = 0; i < 8; i++) {
        int orow = USEIDX ? d_alive[rowBase + r0 + i] : (rowBase + r0 + i);
        *(float4*)&d_H[(size_t)orow * FD + c0] =
            make_float4(acc[i][0], acc[i][1], acc[i][2], acc[i][3]);
        *(float4*)&d_H[(size_t)orow * FD + c0 + 4] =
            make_float4(acc[i][4], acc[i][5], acc[i][6], acc[i][7]);
    }
}

// ---------------- GCN agg: premultiplied H tile, 1 dependent LDS per edge ----------
// hs'[s] = mask_s*dinv_s*h_s; acc_d = sum_e hs'[src_e];
// out_d = relu(dinv_d*(acc_d + hs'[d]) + b)   (alive d: hs'[d] = dinv_d*h_d)
// grid (NB, 2): graph g, feature half hf. 512 threads. 128KB dyn smem.
__global__ void __launch_bounds__(512) k_agg(const float* __restrict__ bias,
                                             const float* __restrict__ p) {
    extern __shared__ float hs[];                    // [512][64] premultiplied
    __shared__ __align__(16) unsigned short csr_s[EPG];
    __shared__ unsigned short off_s[NPG + 1];
    __shared__ float mask_s[NPG], dinv_s[NPG], dinvm_s[NPG];

    int g = blockIdx.x, hf = blockIdx.y;
    int f0 = hf * 64;
    int tid = threadIdx.x;
    int gbase = g * NPG;

    // phase 1: mask, offsets, csr
    mask_s[tid] = d_mask[gbase + tid];
    for (int i = tid; i < NPG + 1; i += 512) off_s[i] = d_goff[g * (NPG + 1) + i];
    {
        const uint4* gp = (const uint4*)(d_csr16 + g * EPG);
        uint4* sp = (uint4*)csr_s;
        for (int j = tid; j < EPG / 8; j += 512) sp[j] = gp[j];
    }
    __syncthreads();

    // phase 2: dinv / dinvm per row
    {
        int e0 = off_s[tid], e1 = off_s[tid + 1];
        float s = 0.f;
        for (int e = e0; e < e1; e++) s += mask_s[csr_s[e]];
        float m = mask_s[tid];
        float deg = m * (1.f + s);
        float dv = rsqrtf(fmaxf(deg, 1.f));
        dinv_s[tid] = dv;
        dinvm_s[tid] = m * dv;
    }
    __syncthreads();

    // phase 3: premultiplied H tile (dead rows -> zeros, no global read)
    for (int idx4 = tid; idx4 < 512 * 16; idx4 += 512) {
        int row = idx4 >> 4, c4 = idx4 & 15;
        float m = dinvm_s[row];
        float4 v = make_float4(0.f, 0.f, 0.f, 0.f);
        if (m != 0.f) {
            v = *(const float4*)&d_H[(size_t)(gbase + row) * FD + f0 + c4 * 4];
            v.x *= m; v.y *= m; v.z *= m; v.w *= m;
        }
        *(float4*)&hs[row * 64 + c4 * 4] = v;
    }
    __syncthreads();

    int w = tid >> 5, lane = tid & 31;
    float b0 = bias[f0 + 2 * lane], b1 = bias[f0 + 2 * lane + 1];
    float p0 = p[f0 + 2 * lane], p1 = p[f0 + 2 * lane + 1];

#pragma unroll 1
    for (int it = 0; it < 32; it++) {
        int d = (w << 5) + it;
        if (mask_s[d] == 0.f) continue;
        float dv = dinv_s[d];
        int e0 = off_s[d], e1 = off_s[d + 1];
        float acc0 = 0.f, acc1 = 0.f;
#pragma unroll 4
        for (int e = e0; e < e1; e++) {
            int sl = csr_s[e];                                   // broadcast LDS.U16
            float2 hv = *(const float2*)&hs[sl * 64 + 2 * lane]; // conflict-free LDS.64
            acc0 += hv.x;
            acc1 += hv.y;
        }
        float2 hd = *(const float2*)&hs[d * 64 + 2 * lane];      // = dv*h_d
        float o0 = fmaxf(fmaf(dv, acc0 + hd.x, b0), 0.f);
        float o1 = fmaxf(fmaf(dv, acc1 + hd.y, b1), 0.f);
        *(float2*)&d_X[(size_t)(gbase + d) * FD + f0 + 2 * lane] = make_float2(o0, o1);
        float part = o0 * p0 + o1 * p1;
#pragma unroll
        for (int o = 16; o > 0; o >>= 1)
            part += __shfl_down_sync(0xffffffffu, part, o);
        if (lane == 0) atomicAdd(&d_sraw[gbase + d], part);
    }
}

// ---------------- top-k (sigmoid + bitonic + mask + alive) FUSED with readout --------
__global__ void __launch_bounds__(512) k_topk(int k, const float* __restrict__ p) {
    __shared__ unsigned long long keys[NPG];
    __shared__ float scs[NPG];
    __shared__ float gate[NPG];
    __shared__ float pp[128];
    __shared__ float smx[4][128], ssm[4][128];
    int g = blockIdx.x, tid = threadIdx.x;
    int gbase = g * NPG;

    if (tid < 128) { float v = p[tid]; pp[tid] = v * v; }
    __syncthreads();
    for (int o = 64; o > 0; o >>= 1) {
        if (tid < o && tid < 64) pp[tid] += pp[tid + o];
        __syncthreads();
    }
    float pinv = rsqrtf(pp[0]);

    {
        int i = tid;
        float m = d_mask[gbase + i];
        float raw = d_sraw[gbase + i];
        d_sraw[gbase + i] = 0.f;
        float sc = 1.f / (1.f + expf(-raw * pinv));
        scs[i] = sc;
        d_score[gbase + i] = sc;
        unsigned int bs = __float_as_uint(sc);
        unsigned int u = (bs & 0x80000000u) ? ~bs : (bs | 0x80000000u);
        if (m == 0.f) u = 0u;
        keys[i] = ((unsigned long long)u << 32) | (unsigned int)(511 - i);
        gate[i] = 0.f;
    }
    __syncthreads();

    for (int ksz = 2; ksz <= NPG; ksz <<= 1) {
        for (int j = ksz >> 1; j > 0; j >>= 1) {
            int ixj = tid ^ j;
            if (ixj > tid) {
                bool asc = (tid & ksz) != 0;
                unsigned long long a = keys[tid], b = keys[ixj];
                if ((a > b) == asc) { keys[tid] = b; keys[ixj] = a; }
            }
            __syncthreads();
        }
    }

    if (tid < k) {
        int i = 511 - (int)(keys[tid] & 0xFFFFFFFFull);
        gate[i] = 1.f;
        d_alive[g * k + tid] = gbase + i;
    }
    __syncthreads();
    d_mask[gbase + tid] = gate[tid];

    // ---- fused readout over the k selected nodes ----
    int f = tid & 127, seg = tid >> 7;                 // 4 segments
    float mx = -1e30f, sm = 0.f;
    for (int j = seg; j < k; j += 4) {
        int i = 511 - (int)(keys[j] & 0xFFFFFFFFull);
        float v = d_X[(size_t)(gbase + i) * FD + f] * scs[i];
        mx = fmaxf(mx, v);
        sm += v;
    }
    smx[seg][f] = mx;
    ssm[seg][f] = sm;
    __syncthreads();
    if (seg == 0) {
#pragma unroll
        for (int s = 1; s < 4; s++) {
            mx = fmaxf(mx, smx[s][f]);
            sm += ssm[s][f];
        }
        d_hg[g * 256 + f]       += fmaxf(mx, 0.f);
        d_hg[g * 256 + 128 + f] += fmaxf(sm / (float)k, 0.f);
    }
}

// ---------------- fused MLP head ----------------
__global__ void __launch_bounds__(256) k_head(const float* __restrict__ inp_c,
                                              const float* __restrict__ We,
                                              const float* __restrict__ Wa,
                                              const float* __restrict__ ba,
                                              const float* __restrict__ Wb,
                                              const float* __restrict__ bb,
                                              const float* __restrict__ Wc,
                                              float* __restrict__ out) {
    __shared__ float fu[320];
    __shared__ float h1[256];
    __shared__ float h2[128];
    __shared__ float red[128];
    int g = blockIdx.x, tid = threadIdx.x;

    if (tid < 64) {
        float a = 0.f;
        for (int i = 0; i < 64; i++) a += inp_c[g * 64 + i] * We[i * 64 + tid];
        fu[tid] = fmaxf(a, 0.f);
    }
    fu[64 + tid] = d_hg[g * 256 + tid];
    __syncthreads();

    float a = ba[tid];
    for (int i = 0; i < 320; i++) a += fu[i] * Wa[i * 256 + tid];
    h1[tid] = fmaxf(a, 0.f);
    __syncthreads();

    if (tid < 128) {
        float c = bb[tid];
        for (int i = 0; i < 256; i++) c += h1[i] * Wb[i * 128 + tid];
        h2[tid] = fmaxf(c, 0.f);
    }
    __syncthreads();

    if (tid < 128) red[tid] = h2[tid] * Wc[tid];
    __syncthreads();
    for (int o = 64; o > 0; o >>= 1) {
        if (tid < o) red[tid] += red[tid + o];
        __syncthreads();
    }
    if (tid == 0) out[g] = red[0];
}

// ---------------- launch ----------------
extern "C" void kernel_launch(void* const* d_in, const int* in_sizes, int n_in,
                              void* d_out, int out_size) {
    const float* x     = (const float*)d_in[0];
    const float* inp_c = (const float*)d_in[1];
    const int*   ei    = (const int*)d_in[2];
    const int*   src   = ei;
    const int*   dst   = ei + EE;
    const float* W1 = (const float*)d_in[4];
    const float* b1 = (const float*)d_in[5];
    const float* W2 = (const float*)d_in[6];
    const float* b2 = (const float*)d_in[7];
    const float* W3 = (const float*)d_in[8];
    const float* b3 = (const float*)d_in[9];
    const float* p1 = (const float*)d_in[10];
    const float* p2 = (const float*)d_in[11];
    const float* p3 = (const float*)d_in[12];
    const float* We = (const float*)d_in[13];
    const float* Wa = (const float*)d_in[14];
    const float* ba = (const float*)d_in[15];
    const float* Wb = (const float*)d_in[16];
    const float* bb = (const float*)d_in[17];
    const float* Wc = (const float*)d_in[18];
    float* out = (float*)d_out;

    cudaFuncSetAttribute((const void*)k_agg,
                         cudaFuncAttributeMaxDynamicSharedMemorySize, 131072);
    size_t aggsm = 512 * 64 * sizeof(float);

    k_init<<<128, 256>>>();
    k_csr<<<NB, 512>>>(src, dst);

    // ---- layer 1 ----
    k_gemm<false, false><<<NN / 128, 256>>>(x, W1);
    k_agg<<<dim3(NB, 2), 512, aggsm>>>(b1, p1);
    k_topk<<<NB, 512>>>(256, p1);

    // ---- layer 2 (32768 alive rows, gated A) ----
    k_gemm<true, true><<<(NB * 256) / 128, 256>>>(nullptr, W2);
    k_agg<<<dim3(NB, 2), 512, aggsm>>>(b2, p2);
    k_topk<<<NB, 512>>>(128, p2);

    // ---- layer 3 (16384 alive rows, gated A) ----
    k_gemm<true, true><<<(NB * 128) / 128, 256>>>(nullptr, W3);
    k_agg<<<dim3(NB, 2), 512, aggsm>>>(b3, p3);
    k_topk<<<NB, 512>>>(64, p3);

    // ---- head ----
    k_head<<<NB, 256>>>(inp_c, We, Wa, ba, Wb, bb, Wc, out);
}

// round 6
// speedup vs baseline: 2.0507x; 1.0742x over previous
#include <cuda_runtime.h>

#define NN 65536      // total nodes
#define EE 1048576    // total edges
#define NB 128        // graphs
#define NPG 512       // nodes per graph
#define EPG 8192      // edges per graph (N*DEG)
#define FD 128        // feature dim

// ---------------- device scratch ----------------
__device__ __align__(256) float d_X[NN * FD];
__device__ __align__(256) float d_H[NN * FD];
__device__ __align__(256) float d_mask[NN];
__device__ __align__(256) float d_score[NN];
__device__ __align__(256) float d_sraw[NN];
__device__ __align__(256) unsigned short d_csr16[EE];
__device__ __align__(256) unsigned short d_goff[NB * (NPG + 1)];
__device__ __align__(256) int   d_alive[NB * 256];
__device__ __align__(256) float d_hg[NB * 256];

// ---------------- init ----------------
__global__ void k_init() {
    int i = blockIdx.x * blockDim.x + threadIdx.x;
    int stride = gridDim.x * blockDim.x;
    for (int j = i; j < NN; j += stride) { d_mask[j] = 1.f; d_sraw[j] = 0.f; }
    for (int j = i; j < NB * 256; j += stride) d_hg[j] = 0.f;
}

// ---------------- per-graph CSR build, all in smem ----------------
__global__ void __launch_bounds__(512) k_csr(const int* __restrict__ src,
                                             const int* __restrict__ dst) {
    __shared__ unsigned short s_src[EPG];
    __shared__ unsigned short s_dst[EPG];
    __shared__ int cnt[NPG];
    __shared__ int scn[NPG];
    __shared__ int cur[NPG];
    int g = blockIdx.x, tid = threadIdx.x;
    int gb = g * NPG, eb = g * EPG;

    cnt[tid] = 0;
    for (int e = tid; e < EPG; e += 512) {
        s_src[e] = (unsigned short)(src[eb + e] - gb);
        s_dst[e] = (unsigned short)(dst[eb + e] - gb);
    }
    __syncthreads();
    for (int e = tid; e < EPG; e += 512) atomicAdd(&cnt[s_dst[e]], 1);
    __syncthreads();
    scn[tid] = cnt[tid];
    __syncthreads();
    for (int o = 1; o < 512; o <<= 1) {
        int a = scn[tid];
        int b = (tid >= o) ? scn[tid - o] : 0;
        __syncthreads();
        scn[tid] = a + b;
        __syncthreads();
    }
    int excl = scn[tid] - cnt[tid];
    cur[tid] = excl;
    d_goff[g * (NPG + 1) + tid] = (unsigned short)excl;
    if (tid == 511) d_goff[g * (NPG + 1) + NPG] = (unsigned short)EPG;
    __syncthreads();
    for (int e = tid; e < EPG; e += 512) {
        int d = s_dst[e];
        int pos = atomicAdd(&cur[d], 1);
        d_csr16[eb + pos] = s_src[e];
    }
}

// ---------------- GEMM: H[rows] = gate*A[rows] @ W (128x128x8, dbl-buffered) ----------
template <bool USEIDX, bool GATE>
__global__ void __launch_bounds__(256) k_gemm(const float* __restrict__ Ain,
                                              const float* __restrict__ W) {
    __shared__ float As[2][8][128];
    __shared__ float Bs[2][8][128];
    const int tid = threadIdx.x;
    const int rowBase = blockIdx.x * 128;

    const int a_r = tid >> 1;
    const int a_k = (tid & 1) * 4;
    int grow = USEIDX ? d_alive[rowBase + a_r] : (rowBase + a_r);
    float gate = 1.f;
    if (GATE) gate = d_score[grow];
    const float* Arow = (USEIDX ? (const float*)d_X : Ain) + (size_t)grow * FD;

    const int b_k = tid >> 5;
    const int b_n = (tid & 31) * 4;
    const int c0 = (tid & 15) * 8;
    const int r0 = (tid >> 4) * 8;

    float4 av = *(const float4*)&Arow[a_k];
    float4 bv = *(const float4*)&W[b_k * FD + b_n];
    if (GATE) { av.x *= gate; av.y *= gate; av.z *= gate; av.w *= gate; }
    As[0][a_k + 0][a_r] = av.x;
    As[0][a_k + 1][a_r] = av.y;
    As[0][a_k + 2][a_r] = av.z;
    As[0][a_k + 3][a_r] = av.w;
    *(float4*)&Bs[0][b_k][b_n] = bv;
    __syncthreads();
    av = *(const float4*)&Arow[8 + a_k];
    bv = *(const float4*)&W[(8 + b_k) * FD + b_n];
    if (GATE) { av.x *= gate; av.y *= gate; av.z *= gate; av.w *= gate; }

    float acc[8][8] = {};
#pragma unroll 1
    for (int it = 0; it < 16; it++) {
        const int buf = it & 1;
#pragma unroll
        for (int kk = 0; kk < 8; kk++) {
            float a0[8], b0[8];
            *(float4*)&a0[0] = *(float4*)&As[buf][kk][r0];
            *(float4*)&a0[4] = *(float4*)&As[buf][kk][r0 + 4];
            *(float4*)&b0[0] = *(float4*)&Bs[buf][kk][c0];
            *(float4*)&b0[4] = *(float4*)&Bs[buf][kk][c0 + 4];
#pragma unroll
            for (int i = 0; i < 8; i++)
#pragma unroll
                for (int j = 0; j < 8; j++) acc[i][j] += a0[i] * b0[j];
        }
        if (it < 15) {
            const int nb = buf ^ 1;
            As[nb][a_k + 0][a_r] = av.x;
            As[nb][a_k + 1][a_r] = av.y;
            As[nb][a_k + 2][a_r] = av.z;
            As[nb][a_k + 3][a_r] = av.w;
            *(float4*)&Bs[nb][b_k][b_n] = bv;
            __syncthreads();
            if (it < 14) {
                int k0 = (it + 2) * 8;
                av = *(const float4*)&Arow[k0 + a_k];
                bv = *(const float4*)&W[(k0 + b_k) * FD + b_n];
                if (GATE) { av.x *= gate; av.y *= gate; av.z *= gate; av.w *= gate; }
            }
        }
    }
#pragma unroll
    for (int i = 0; i < 8; i++) {
        int orow = USEIDX ? d_alive[rowBase + r0 + i] : (rowBase + r0 + i);
        *(float4*)&d_H[(size_t)orow * FD + c0] =
            make_float4(acc[i][0], acc[i][1], acc[i][2], acc[i][3]);
        *(float4*)&d_H[(size_t)orow * FD + c0 + 4] =
            make_float4(acc[i][4], acc[i][5], acc[i][6], acc[i][7]);
    }
}

// ---------------- GCN agg: premultiplied H tile, 1024 threads (32 warps) ----------
// hs'[s] = mask_s*dinv_s*h_s; acc_d = sum_e hs'[src_e];
// out_d = relu(dinv_d*(acc_d + hs'[d]) + b)
// grid (NB, 2): graph g, feature half hf. 1024 threads. 128KB dyn smem.
__global__ void __launch_bounds__(1024) k_agg(const float* __restrict__ bias,
                                              const float* __restrict__ p) {
    extern __shared__ float hs[];                    // [512][64] premultiplied
    __shared__ __align__(16) unsigned short csr_s[EPG];
    __shared__ unsigned short off_s[NPG + 1];
    __shared__ float mask_s[NPG], dinv_s[NPG], dinvm_s[NPG];

    int g = blockIdx.x, hf = blockIdx.y;
    int f0 = hf * 64;
    int tid = threadIdx.x;
    int gbase = g * NPG;

    // phase 1: mask, offsets, csr
    if (tid < NPG) mask_s[tid] = d_mask[gbase + tid];
    if (tid < NPG + 1) off_s[tid] = d_goff[g * (NPG + 1) + tid];
    {
        const uint4* gp = (const uint4*)(d_csr16 + g * EPG);
        uint4* sp = (uint4*)csr_s;
        sp[tid] = gp[tid];                            // EPG/8 = 1024 exactly
    }
    __syncthreads();

    // phase 2: dinv / dinvm per row
    if (tid < NPG) {
        int e0 = off_s[tid], e1 = off_s[tid + 1];
        float s = 0.f;
        for (int e = e0; e < e1; e++) s += mask_s[csr_s[e]];
        float m = mask_s[tid];
        float deg = m * (1.f + s);
        float dv = rsqrtf(fmaxf(deg, 1.f));
        dinv_s[tid] = dv;
        dinvm_s[tid] = m * dv;
    }
    __syncthreads();

    // phase 3: premultiplied H tile (dead rows -> zeros, no global read)
    for (int idx4 = tid; idx4 < 512 * 16; idx4 += 1024) {
        int row = idx4 >> 4, c4 = idx4 & 15;
        float m = dinvm_s[row];
        float4 v = make_float4(0.f, 0.f, 0.f, 0.f);
        if (m != 0.f) {
            v = *(const float4*)&d_H[(size_t)(gbase + row) * FD + f0 + c4 * 4];
            v.x *= m; v.y *= m; v.z *= m; v.w *= m;
        }
        *(float4*)&hs[row * 64 + c4 * 4] = v;
    }
    __syncthreads();

    int w = tid >> 5, lane = tid & 31;               // 32 warps, 16 rows each
    float b0 = bias[f0 + 2 * lane], b1 = bias[f0 + 2 * lane + 1];
    float p0 = p[f0 + 2 * lane], p1 = p[f0 + 2 * lane + 1];

#pragma unroll 1
    for (int it = 0; it < 16; it++) {
        int d = (w << 4) + it;
        if (mask_s[d] == 0.f) continue;
        float dv = dinv_s[d];
        int e0 = off_s[d], e1 = off_s[d + 1];
        float acc0 = 0.f, acc1 = 0.f;
#pragma unroll 4
        for (int e = e0; e < e1; e++) {
            int sl = csr_s[e];                                   // broadcast LDS.U16
            float2 hv = *(const float2*)&hs[sl * 64 + 2 * lane]; // conflict-free LDS.64
            acc0 += hv.x;
            acc1 += hv.y;
        }
        float2 hd = *(const float2*)&hs[d * 64 + 2 * lane];      // = dv*h_d
        float o0 = fmaxf(fmaf(dv, acc0 + hd.x, b0), 0.f);
        float o1 = fmaxf(fmaf(dv, acc1 + hd.y, b1), 0.f);
        *(float2*)&d_X[(size_t)(gbase + d) * FD + f0 + 2 * lane] = make_float2(o0, o1);
        float part = o0 * p0 + o1 * p1;
#pragma unroll
        for (int o = 16; o > 0; o >>= 1)
            part += __shfl_down_sync(0xffffffffu, part, o);
        if (lane == 0) atomicAdd(&d_sraw[gbase + d], part);
    }
}

// ---------------- top-k (sigmoid + bitonic + mask + alive) FUSED with readout --------
__global__ void __launch_bounds__(512) k_topk(int k, const float* __restrict__ p) {
    __shared__ unsigned long long keys[NPG];
    __shared__ float scs[NPG];
    __shared__ float gate[NPG];
    __shared__ float pp[128];
    __shared__ float smx[4][128], ssm[4][128];
    int g = blockIdx.x, tid = threadIdx.x;
    int gbase = g * NPG;

    if (tid < 128) { float v = p[tid]; pp[tid] = v * v; }
    __syncthreads();
    for (int o = 64; o > 0; o >>= 1) {
        if (tid < o && tid < 64) pp[tid] += pp[tid + o];
        __syncthreads();
    }
    float pinv = rsqrtf(pp[0]);

    {
        int i = tid;
        float m = d_mask[gbase + i];
        float raw = d_sraw[gbase + i];
        d_sraw[gbase + i] = 0.f;
        float sc = 1.f / (1.f + expf(-raw * pinv));
        scs[i] = sc;
        d_score[gbase + i] = sc;
        unsigned int bs = __float_as_uint(sc);
        unsigned int u = (bs & 0x80000000u) ? ~bs : (bs | 0x80000000u);
        if (m == 0.f) u = 0u;
        keys[i] = ((unsigned long long)u << 32) | (unsigned int)(511 - i);
        gate[i] = 0.f;
    }
    __syncthreads();

    for (int ksz = 2; ksz <= NPG; ksz <<= 1) {
        for (int j = ksz >> 1; j > 0; j >>= 1) {
            int ixj = tid ^ j;
            if (ixj > tid) {
                bool asc = (tid & ksz) != 0;
                unsigned long long a = keys[tid], b = keys[ixj];
                if ((a > b) == asc) { keys[tid] = b; keys[ixj] = a; }
            }
            __syncthreads();
        }
    }

    if (tid < k) {
        int i = 511 - (int)(keys[tid] & 0xFFFFFFFFull);
        gate[i] = 1.f;
        d_alive[g * k + tid] = gbase + i;
    }
    __syncthreads();
    d_mask[gbase + tid] = gate[tid];

    // ---- fused readout over the k selected nodes ----
    int f = tid & 127, seg = tid >> 7;                 // 4 segments
    float mx = -1e30f, sm = 0.f;
    for (int j = seg; j < k; j += 4) {
        int i = 511 - (int)(keys[j] & 0xFFFFFFFFull);
        float v = d_X[(size_t)(gbase + i) * FD + f] * scs[i];
        mx = fmaxf(mx, v);
        sm += v;
    }
    smx[seg][f] = mx;
    ssm[seg][f] = sm;
    __syncthreads();
    if (seg == 0) {
#pragma unroll
        for (int s = 1; s < 4; s++) {
            mx = fmaxf(mx, smx[s][f]);
            sm += ssm[s][f];
        }
        d_hg[g * 256 + f]       += fmaxf(mx, 0.f);
        d_hg[g * 256 + 128 + f] += fmaxf(sm / (float)k, 0.f);
    }
}

// ---------------- fused MLP head ----------------
__global__ void __launch_bounds__(256) k_head(const float* __restrict__ inp_c,
                                              const float* __restrict__ We,
                                              const float* __restrict__ Wa,
                                              const float* __restrict__ ba,
                                              const float* __restrict__ Wb,
                                              const float* __restrict__ bb,
                                              const float* __restrict__ Wc,
                                              float* __restrict__ out) {
    __shared__ float fu[320];
    __shared__ float h1[256];
    __shared__ float h2[128];
    __shared__ float red[128];
    int g = blockIdx.x, tid = threadIdx.x;

    if (tid < 64) {
        float a = 0.f;
        for (int i = 0; i < 64; i++) a += inp_c[g * 64 + i] * We[i * 64 + tid];
        fu[tid] = fmaxf(a, 0.f);
    }
    fu[64 + tid] = d_hg[g * 256 + tid];
    __syncthreads();

    float a = ba[tid];
    for (int i = 0; i < 320; i++) a += fu[i] * Wa[i * 256 + tid];
    h1[tid] = fmaxf(a, 0.f);
    __syncthreads();

    if (tid < 128) {
        float c = bb[tid];
        for (int i = 0; i < 256; i++) c += h1[i] * Wb[i * 128 + tid];
        h2[tid] = fmaxf(c, 0.f);
    }
    __syncthreads();

    if (tid < 128) red[tid] = h2[tid] * Wc[tid];
    __syncthreads();
    for (int o = 64; o > 0; o >>= 1) {
        if (tid < o) red[tid] += red[tid + o];
        __syncthreads();
    }
    if (tid == 0) out[g] = red[0];
}

// ---------------- launch ----------------
extern "C" void kernel_launch(void* const* d_in, const int* in_sizes, int n_in,
                              void* d_out, int out_size) {
    const float* x     = (const float*)d_in[0];
    const float* inp_c = (const float*)d_in[1];
    const int*   ei    = (const int*)d_in[2];
    const int*   src   = ei;
    const int*   dst   = ei + EE;
    const float* W1 = (const float*)d_in[4];
    const float* b1 = (const float*)d_in[5];
    const float* W2 = (const float*)d_in[6];
    const float* b2 = (const float*)d_in[7];
    const float* W3 = (const float*)d_in[8];
    const float* b3 = (const float*)d_in[9];
    const float* p1 = (const float*)d_in[10];
    const float* p2 = (const float*)d_in[11];
    const float* p3 = (const float*)d_in[12];
    const float* We = (const float*)d_in[13];
    const float* Wa = (const float*)d_in[14];
    const float* ba = (const float*)d_in[15];
    const float* Wb = (const float*)d_in[16];
    const float* bb = (const float*)d_in[17];
    const float* Wc = (const float*)d_in[18];
    float* out = (float*)d_out;

    cudaFuncSetAttribute((const void*)k_agg,
                         cudaFuncAttributeMaxDynamicSharedMemorySize, 131072);
    size_t aggsm = 512 * 64 * sizeof(float);

    k_init<<<128, 256>>>();
    k_csr<<<NB, 512>>>(src, dst);

    // ---- layer 1 ----
    k_gemm<false, false><<<NN / 128, 256>>>(x, W1);
    k_agg<<<dim3(NB, 2), 1024, aggsm>>>(b1, p1);
    k_topk<<<NB, 512>>>(256, p1);

    // ---- layer 2 (32768 alive rows, gated A) ----
    k_gemm<true, true><<<(NB * 256) / 128, 256>>>(nullptr, W2);
    k_agg<<<dim3(NB, 2), 1024, aggsm>>>(b2, p2);
    k_topk<<<NB, 512>>>(128, p2);

    // ---- layer 3 (16384 alive rows, gated A) ----
    k_gemm<true, true><<<(NB * 128) / 128, 256>>>(nullptr, W3);
    k_agg<<<dim3(NB, 2), 1024, aggsm>>>(b3, p3);
    k_topk<<<NB, 512>>>(64, p3);

    // ---- head ----
    k_head<<<NB, 256>>>(inp_c, We, Wa, ba, Wb, bb, Wc, out);
}

// round 7
// speedup vs baseline: 2.3595x; 1.1506x over previous
#include <cuda_runtime.h>
#include <cuda_bf16.h>

#define NN 65536      // total nodes
#define EE 1048576    // total edges
#define NB 128        // graphs
#define NPG 512       // nodes per graph
#define EPG 8192      // edges per graph (N*DEG)
#define FD 128        // feature dim

// ---------------- device scratch ----------------
__device__ __align__(256) float d_X[NN * FD];
__device__ __align__(256) float d_H[NN * FD];
__device__ __align__(256) float d_mask[NN];
__device__ __align__(256) float d_score[NN];
__device__ __align__(256) float d_sraw[NN];
__device__ __align__(256) unsigned short d_csr16[EE];
__device__ __align__(256) unsigned short d_goff[NB * (NPG + 1)];
__device__ __align__(256) int   d_alive[NB * 256];
__device__ __align__(256) float d_hg[NB * 256];

// ---------------- init ----------------
__global__ void k_init() {
    int i = blockIdx.x * blockDim.x + threadIdx.x;
    int stride = gridDim.x * blockDim.x;
    for (int j = i; j < NN; j += stride) { d_mask[j] = 1.f; d_sraw[j] = 0.f; }
    for (int j = i; j < NB * 256; j += stride) d_hg[j] = 0.f;
}

// ---------------- per-graph CSR build, all in smem ----------------
__global__ void __launch_bounds__(512) k_csr(const int* __restrict__ src,
                                             const int* __restrict__ dst) {
    __shared__ unsigned short s_src[EPG];
    __shared__ unsigned short s_dst[EPG];
    __shared__ int cnt[NPG];
    __shared__ int scn[NPG];
    __shared__ int cur[NPG];
    int g = blockIdx.x, tid = threadIdx.x;
    int gb = g * NPG, eb = g * EPG;

    cnt[tid] = 0;
    for (int e = tid; e < EPG; e += 512) {
        s_src[e] = (unsigned short)(src[eb + e] - gb);
        s_dst[e] = (unsigned short)(dst[eb + e] - gb);
    }
    __syncthreads();
    for (int e = tid; e < EPG; e += 512) atomicAdd(&cnt[s_dst[e]], 1);
    __syncthreads();
    scn[tid] = cnt[tid];
    __syncthreads();
    for (int o = 1; o < 512; o <<= 1) {
        int a = scn[tid];
        int b = (tid >= o) ? scn[tid - o] : 0;
        __syncthreads();
        scn[tid] = a + b;
        __syncthreads();
    }
    int excl = scn[tid] - cnt[tid];
    cur[tid] = excl;
    d_goff[g * (NPG + 1) + tid] = (unsigned short)excl;
    if (tid == 511) d_goff[g * (NPG + 1) + NPG] = (unsigned short)EPG;
    __syncthreads();
    for (int e = tid; e < EPG; e += 512) {
        int d = s_dst[e];
        int pos = atomicAdd(&cur[d], 1);
        d_csr16[eb + pos] = s_src[e];
    }
}

// ---------------- tensor-core GEMM: H[rows] = gate*A[rows] @ W -------------------
// bf16-split 3-pass (Ahi@Whi + Ahi@Wlo + Alo@Whi) ~ fp32 precision.
// Block tile 128x128, K in 4 chunks of 32. 8 warps = 4(m) x 2(n), warp tile 32x64.
__device__ __forceinline__ void ldsm_x4(unsigned addr, unsigned& r0, unsigned& r1,
                                        unsigned& r2, unsigned& r3) {
    asm volatile("ldmatrix.sync.aligned.m8n8.x4.shared.b16 {%0,%1,%2,%3}, [%4];"
                 : "=r"(r0), "=r"(r1), "=r"(r2), "=r"(r3) : "r"(addr));
}
__device__ __forceinline__ void ldsm_x4t(unsigned addr, unsigned& r0, unsigned& r1,
                                         unsigned& r2, unsigned& r3) {
    asm volatile("ldmatrix.sync.aligned.m8n8.x4.trans.shared.b16 {%0,%1,%2,%3}, [%4];"
                 : "=r"(r0), "=r"(r1), "=r"(r2), "=r"(r3) : "r"(addr));
}
__device__ __forceinline__ void mma16816(float* c, unsigned a0, unsigned a1,
                                         unsigned a2, unsigned a3,
                                         unsigned b0, unsigned b1) {
    asm volatile(
        "mma.sync.aligned.m16n8k16.row.col.f32.bf16.bf16.f32 "
        "{%0,%1,%2,%3},{%4,%5,%6,%7},{%8,%9},{%0,%1,%2,%3};"
        : "+f"(c[0]), "+f"(c[1]), "+f"(c[2]), "+f"(c[3])
        : "r"(a0), "r"(a1), "r"(a2), "r"(a3), "r"(b0), "r"(b1));
}

#define APAD 40   // A smem row length (32 used)
#define WPAD 136  // W smem row length (128 used)

template <bool USEIDX, bool GATE>
__global__ void __launch_bounds__(256) k_gemm(const float* __restrict__ Ain,
                                              const float* __restrict__ W) {
    __shared__ __align__(16) __nv_bfloat16 As[2][128][APAD];  // [hi/lo][m][k]
    __shared__ __align__(16) __nv_bfloat16 Ws[2][32][WPAD];   // [hi/lo][k][n]
    __shared__ int alive_s[128];

    const int tid = threadIdx.x;
    const int gbase = blockIdx.x * 128;

    if (USEIDX && tid < 128) alive_s[tid] = d_alive[gbase + tid];

    // loader mapping: A: thread -> (row, 16-k half); W: thread -> (k, 16-n span)
    const int al_r = tid >> 1, al_k = (tid & 1) * 16;
    const int wl_k = tid >> 3, wl_n = (tid & 7) * 16;
    int garow = USEIDX ? d_alive[gbase + al_r] : (gbase + al_r);
    float gate = GATE ? d_score[garow] : 1.f;
    const float* Arow = (USEIDX ? (const float*)d_X : Ain) + (size_t)garow * FD;

    const int lane = tid & 31, wid = tid >> 5;
    const int m0 = (wid >> 1) * 32;      // 4 m-warps
    const int n0 = (wid & 1) * 64;       // 2 n-warps
    const int quad = lane >> 3, r8 = lane & 7;

    float acc[2][8][4] = {};

#pragma unroll 1
    for (int ck = 0; ck < 4; ck++) {
        if (ck) __syncthreads();
        // ---- stage A (gated, split hi/lo) ----
        {
            const float* src = Arow + ck * 32 + al_k;
#pragma unroll
            for (int q = 0; q < 4; q++) {
                float4 v = *(const float4*)&src[q * 4];
                if (GATE) { v.x *= gate; v.y *= gate; v.z *= gate; v.w *= gate; }
                float f[4] = {v.x, v.y, v.z, v.w};
#pragma unroll
                for (int i = 0; i < 4; i++) {
                    __nv_bfloat16 h = __float2bfloat16(f[i]);
                    __nv_bfloat16 l = __float2bfloat16(f[i] - __bfloat162float(h));
                    As[0][al_r][al_k + q * 4 + i] = h;
                    As[1][al_r][al_k + q * 4 + i] = l;
                }
            }
        }
        // ---- stage W (split hi/lo) ----
        {
            const float* src = W + (size_t)(ck * 32 + wl_k) * FD + wl_n;
#pragma unroll
            for (int q = 0; q < 4; q++) {
                float4 v = *(const float4*)&src[q * 4];
                float f[4] = {v.x, v.y, v.z, v.w};
#pragma unroll
                for (int i = 0; i < 4; i++) {
                    __nv_bfloat16 h = __float2bfloat16(f[i]);
                    __nv_bfloat16 l = __float2bfloat16(f[i] - __bfloat162float(h));
                    Ws[0][wl_k][wl_n + q * 4 + i] = h;
                    Ws[1][wl_k][wl_n + q * 4 + i] = l;
                }
            }
        }
        __syncthreads();

#pragma unroll
        for (int ks = 0; ks < 32; ks += 16) {
            // A fragments: [ver][mtile][4]
            unsigned af[2][2][4];
#pragma unroll
            for (int v = 0; v < 2; v++)
#pragma unroll
                for (int mt = 0; mt < 2; mt++) {
                    int arow = m0 + mt * 16 + ((quad & 1) << 3) + r8;
                    int acol = ks + ((quad >> 1) << 3);
                    unsigned addr = (unsigned)__cvta_generic_to_shared(
                        &As[v][arow][acol]);
                    ldsm_x4(addr, af[v][mt][0], af[v][mt][1], af[v][mt][2], af[v][mt][3]);
                }
            // B fragments: [ver][ntile(8)][2]
            unsigned bf[2][8][2];
#pragma unroll
            for (int v = 0; v < 2; v++)
#pragma unroll
                for (int nb = 0; nb < 4; nb++) {
                    int brow = ks + ((quad & 1) << 3) + r8;
                    int bcol = n0 + nb * 16 + ((quad >> 1) << 3);
                    unsigned addr = (unsigned)__cvta_generic_to_shared(
                        &Ws[v][brow][bcol]);
                    unsigned r0, r1, r2, r3;
                    ldsm_x4t(addr, r0, r1, r2, r3);
                    bf[v][nb * 2 + 0][0] = r0; bf[v][nb * 2 + 0][1] = r1;
                    bf[v][nb * 2 + 1][0] = r2; bf[v][nb * 2 + 1][1] = r3;
                }
            // mma: hi*hi + hi*lo + lo*hi
#pragma unroll
            for (int mt = 0; mt < 2; mt++)
#pragma unroll
                for (int nt = 0; nt < 8; nt++) {
                    float* c = acc[mt][nt];
                    mma16816(c, af[0][mt][0], af[0][mt][1], af[0][mt][2], af[0][mt][3],
                             bf[0][nt][0], bf[0][nt][1]);
                    mma16816(c, af[0][mt][0], af[0][mt][1], af[0][mt][2], af[0][mt][3],
                             bf[1][nt][0], bf[1][nt][1]);
                    mma16816(c, af[1][mt][0], af[1][mt][1], af[1][mt][2], af[1][mt][3],
                             bf[0][nt][0], bf[0][nt][1]);
                }
        }
    }

    // ---- store C ----
#pragma unroll
    for (int mt = 0; mt < 2; mt++) {
        int lr = m0 + mt * 16 + (lane >> 2);
        int gr0 = USEIDX ? alive_s[lr] : (gbase + lr);
        int gr1 = USEIDX ? alive_s[lr + 8] : (gbase + lr + 8);
#pragma unroll
        for (int nt = 0; nt < 8; nt++) {
            int col = n0 + nt * 8 + ((lane & 3) << 1);
            float* c = acc[mt][nt];
            *(float2*)&d_H[(size_t)gr0 * FD + col] = make_float2(c[0], c[1]);
            *(float2*)&d_H[(size_t)gr1 * FD + col] = make_float2(c[2], c[3]);
        }
    }
}

// ---------------- GCN agg: premultiplied H tile, 1024 threads (32 warps) ----------
__global__ void __launch_bounds__(1024) k_agg(const float* __restrict__ bias,
                                              const float* __restrict__ p) {
    extern __shared__ float hs[];                    // [512][64] premultiplied
    __shared__ __align__(16) unsigned short csr_s[EPG];
    __shared__ unsigned short off_s[NPG + 1];
    __shared__ float mask_s[NPG], dinv_s[NPG], dinvm_s[NPG];

    int g = blockIdx.x, hf = blockIdx.y;
    int f0 = hf * 64;
    int tid = threadIdx.x;
    int gbase = g * NPG;

    if (tid < NPG) mask_s[tid] = d_mask[gbase + tid];
    if (tid < NPG + 1) off_s[tid] = d_goff[g * (NPG + 1) + tid];
    {
        const uint4* gp = (const uint4*)(d_csr16 + g * EPG);
        uint4* sp = (uint4*)csr_s;
        sp[tid] = gp[tid];
    }
    __syncthreads();

    if (tid < NPG) {
        int e0 = off_s[tid], e1 = off_s[tid + 1];
        float s = 0.f;
        for (int e = e0; e < e1; e++) s += mask_s[csr_s[e]];
        float m = mask_s[tid];
        float deg = m * (1.f + s);
        float dv = rsqrtf(fmaxf(deg, 1.f));
        dinv_s[tid] = dv;
        dinvm_s[tid] = m * dv;
    }
    __syncthreads();

    for (int idx4 = tid; idx4 < 512 * 16; idx4 += 1024) {
        int row = idx4 >> 4, c4 = idx4 & 15;
        float m = dinvm_s[row];
        float4 v = make_float4(0.f, 0.f, 0.f, 0.f);
        if (m != 0.f) {
            v = *(const float4*)&d_H[(size_t)(gbase + row) * FD + f0 + c4 * 4];
            v.x *= m; v.y *= m; v.z *= m; v.w *= m;
        }
        *(float4*)&hs[row * 64 + c4 * 4] = v;
    }
    __syncthreads();

    int w = tid >> 5, lane = tid & 31;
    float b0 = bias[f0 + 2 * lane], b1 = bias[f0 + 2 * lane + 1];
    float p0 = p[f0 + 2 * lane], p1 = p[f0 + 2 * lane + 1];

#pragma unroll 1
    for (int it = 0; it < 16; it++) {
        int d = (w << 4) + it;
        if (mask_s[d] == 0.f) continue;
        float dv = dinv_s[d];
        int e0 = off_s[d], e1 = off_s[d + 1];
        float acc0 = 0.f, acc1 = 0.f;
#pragma unroll 4
        for (int e = e0; e < e1; e++) {
            int sl = csr_s[e];
            float2 hv = *(const float2*)&hs[sl * 64 + 2 * lane];
            acc0 += hv.x;
            acc1 += hv.y;
        }
        float2 hd = *(const float2*)&hs[d * 64 + 2 * lane];
        float o0 = fmaxf(fmaf(dv, acc0 + hd.x, b0), 0.f);
        float o1 = fmaxf(fmaf(dv, acc1 + hd.y, b1), 0.f);
        *(float2*)&d_X[(size_t)(gbase + d) * FD + f0 + 2 * lane] = make_float2(o0, o1);
        float part = o0 * p0 + o1 * p1;
#pragma unroll
        for (int o = 16; o > 0; o >>= 1)
            part += __shfl_down_sync(0xffffffffu, part, o);
        if (lane == 0) atomicAdd(&d_sraw[gbase + d], part);
    }
}

// ---------------- top-k (sigmoid + bitonic + mask + alive) FUSED with readout --------
__global__ void __launch_bounds__(512) k_topk(int k, const float* __restrict__ p) {
    __shared__ unsigned long long keys[NPG];
    __shared__ float scs[NPG];
    __shared__ float gate[NPG];
    __shared__ float pp[128];
    __shared__ float smx[4][128], ssm[4][128];
    int g = blockIdx.x, tid = threadIdx.x;
    int gbase = g * NPG;

    if (tid < 128) { float v = p[tid]; pp[tid] = v * v; }
    __syncthreads();
    for (int o = 64; o > 0; o >>= 1) {
        if (tid < o && tid < 64) pp[tid] += pp[tid + o];
        __syncthreads();
    }
    float pinv = rsqrtf(pp[0]);

    {
        int i = tid;
        float m = d_mask[gbase + i];
        float raw = d_sraw[gbase + i];
        d_sraw[gbase + i] = 0.f;
        float sc = 1.f / (1.f + expf(-raw * pinv));
        scs[i] = sc;
        d_score[gbase + i] = sc;
        unsigned int bs = __float_as_uint(sc);
        unsigned int u = (bs & 0x80000000u) ? ~bs : (bs | 0x80000000u);
        if (m == 0.f) u = 0u;
        keys[i] = ((unsigned long long)u << 32) | (unsigned int)(511 - i);
        gate[i] = 0.f;
    }
    __syncthreads();

    for (int ksz = 2; ksz <= NPG; ksz <<= 1) {
        for (int j = ksz >> 1; j > 0; j >>= 1) {
            int ixj = tid ^ j;
            if (ixj > tid) {
                bool asc = (tid & ksz) != 0;
                unsigned long long a = keys[tid], b = keys[ixj];
                if ((a > b) == asc) { keys[tid] = b; keys[ixj] = a; }
            }
            __syncthreads();
        }
    }

    if (tid < k) {
        int i = 511 - (int)(keys[tid] & 0xFFFFFFFFull);
        gate[i] = 1.f;
        d_alive[g * k + tid] = gbase + i;
    }
    __syncthreads();
    d_mask[gbase + tid] = gate[tid];

    int f = tid & 127, seg = tid >> 7;
    float mx = -1e30f, sm = 0.f;
    for (int j = seg; j < k; j += 4) {
        int i = 511 - (int)(keys[j] & 0xFFFFFFFFull);
        float v = d_X[(size_t)(gbase + i) * FD + f] * scs[i];
        mx = fmaxf(mx, v);
        sm += v;
    }
    smx[seg][f] = mx;
    ssm[seg][f] = sm;
    __syncthreads();
    if (seg == 0) {
#pragma unroll
        for (int s = 1; s < 4; s++) {
            mx = fmaxf(mx, smx[s][f]);
            sm += ssm[s][f];
        }
        d_hg[g * 256 + f]       += fmaxf(mx, 0.f);
        d_hg[g * 256 + 128 + f] += fmaxf(sm / (float)k, 0.f);
    }
}

// ---------------- fused MLP head ----------------
__global__ void __launch_bounds__(256) k_head(const float* __restrict__ inp_c,
                                              const float* __restrict__ We,
                                              const float* __restrict__ Wa,
                                              const float* __restrict__ ba,
                                              const float* __restrict__ Wb,
                                              const float* __restrict__ bb,
                                              const float* __restrict__ Wc,
                                              float* __restrict__ out) {
    __shared__ float fu[320];
    __shared__ float h1[256];
    __shared__ float h2[128];
    __shared__ float red[128];
    int g = blockIdx.x, tid = threadIdx.x;

    if (tid < 64) {
        float a = 0.f;
        for (int i = 0; i < 64; i++) a += inp_c[g * 64 + i] * We[i * 64 + tid];
        fu[tid] = fmaxf(a, 0.f);
    }
    fu[64 + tid] = d_hg[g * 256 + tid];
    __syncthreads();

    float a = ba[tid];
    for (int i = 0; i < 320; i++) a += fu[i] * Wa[i * 256 + tid];
    h1[tid] = fmaxf(a, 0.f);
    __syncthreads();

    if (tid < 128) {
        float c = bb[tid];
        for (int i = 0; i < 256; i++) c += h1[i] * Wb[i * 128 + tid];
        h2[tid] = fmaxf(c, 0.f);
    }
    __syncthreads();

    if (tid < 128) red[tid] = h2[tid] * Wc[tid];
    __syncthreads();
    for (int o = 64; o > 0; o >>= 1) {
        if (tid < o) red[tid] += red[tid + o];
        __syncthreads();
    }
    if (tid == 0) out[g] = red[0];
}

// ---------------- launch ----------------
extern "C" void kernel_launch(void* const* d_in, const int* in_sizes, int n_in,
                              void* d_out, int out_size) {
    const float* x     = (const float*)d_in[0];
    const float* inp_c = (const float*)d_in[1];
    const int*   ei    = (const int*)d_in[2];
    const int*   src   = ei;
    const int*   dst   = ei + EE;
    const float* W1 = (const float*)d_in[4];
    const float* b1 = (const float*)d_in[5];
    const float* W2 = (const float*)d_in[6];
    const float* b2 = (const float*)d_in[7];
    const float* W3 = (const float*)d_in[8];
    const float* b3 = (const float*)d_in[9];
    const float* p1 = (const float*)d_in[10];
    const float* p2 = (const float*)d_in[11];
    const float* p3 = (const float*)d_in[12];
    const float* We = (const float*)d_in[13];
    const float* Wa = (const float*)d_in[14];
    const float* ba = (const float*)d_in[15];
    const float* Wb = (const float*)d_in[16];
    const float* bb = (const float*)d_in[17];
    const float* Wc = (const float*)d_in[18];
    float* out = (float*)d_out;

    cudaFuncSetAttribute((const void*)k_agg,
                         cudaFuncAttributeMaxDynamicSharedMemorySize, 131072);
    size_t aggsm = 512 * 64 * sizeof(float);

    k_init<<<128, 256>>>();
    k_csr<<<NB, 512>>>(src, dst);

    // ---- layer 1 ----
    k_gemm<false, false><<<NN / 128, 256>>>(x, W1);
    k_agg<<<dim3(NB, 2), 1024, aggsm>>>(b1, p1);
    k_topk<<<NB, 512>>>(256, p1);

    // ---- layer 2 (32768 alive rows, gated A) ----
    k_gemm<true, true><<<(NB * 256) / 128, 256>>>(nullptr, W2);
    k_agg<<<dim3(NB, 2), 1024, aggsm>>>(b2, p2);
    k_topk<<<NB, 512>>>(128, p2);

    // ---- layer 3 (16384 alive rows, gated A) ----
    k_gemm<true, true><<<(NB * 128) / 128, 256>>>(nullptr, W3);
    k_agg<<<dim3(NB, 2), 1024, aggsm>>>(b3, p3);
    k_topk<<<NB, 512>>>(64, p3);

    // ---- head ----
    k_head<<<NB, 256>>>(inp_c, We, Wa, ba, Wb, bb, Wc, out);
}